// round 8
// baseline (speedup 1.0000x reference)
#include <cuda_runtime.h>
#include <cuda_bf16.h>
#include <math.h>
#include <stdint.h>

// ---------------------------------------------------------------------------
// Problem constants
// ---------------------------------------------------------------------------
#define BB 4
#define SS 4096
#define DD 1024
#define HH 16
#define FF 256
#define HD 64
#define NN (BB * SS)          // 16384 rows
#define GK 1024               // GEMM K

// ---------------------------------------------------------------------------
// Scratch (device globals; no allocations allowed)
// ---------------------------------------------------------------------------
__device__ __nv_bfloat16 g_xh[NN * DD];
__device__ __nv_bfloat16 g_xl[NN * DD];
__device__ __nv_bfloat16 g_wh[4 * DD * DD];
__device__ __nv_bfloat16 g_wl[4 * DD * DD];
__device__ __nv_bfloat16 g_rfh[HH * HD * FF];
__device__ __nv_bfloat16 g_rfl[HH * HD * FF];

__device__ __nv_bfloat16 g_qh[NN * DD];
__device__ __nv_bfloat16 g_ql[NN * DD];
__device__ __nv_bfloat16 g_kh[NN * DD];
__device__ __nv_bfloat16 g_kl[NN * DD];
__device__ __nv_bfloat16 g_vh[NN * DD];
__device__ __nv_bfloat16 g_vl[NN * DD];
__device__ __nv_bfloat16 g_yh[NN * DD];
__device__ __nv_bfloat16 g_yl[NN * DD];

__device__ __nv_bfloat16 g_qph[(size_t)BB * HH * SS * FF];
__device__ __nv_bfloat16 g_qpl[(size_t)BB * HH * SS * FF];
__device__ __nv_bfloat16 g_kph[(size_t)BB * HH * SS * FF];
__device__ __nv_bfloat16 g_kpl[(size_t)BB * HH * SS * FF];

__device__ float g_kv[(size_t)BB * HH * FF * HD];     // fp32 (atomics)
__device__ float g_ksum[(size_t)BB * HH * FF];
// extended kv: 72 cols = kv(64) | ksum(1) | zeros(7), split hi/lo
__device__ __nv_bfloat16 g_kvh[(size_t)BB * HH * FF * 72];
__device__ __nv_bfloat16 g_kvl[(size_t)BB * HH * FF * 72];

// ---------------------------------------------------------------------------
// PTX helpers (base-target: cp.async / ldmatrix / mma.sync)
// ---------------------------------------------------------------------------
__device__ __forceinline__ uint32_t smem_u32(const void* p) {
    return (uint32_t)__cvta_generic_to_shared(p);
}
__device__ __forceinline__ void cp_async16(uint32_t dst, const void* src) {
    asm volatile("cp.async.cg.shared.global [%0], [%1], 16;"
                 :: "r"(dst), "l"(src) : "memory");
}
__device__ __forceinline__ void ldm_x4(uint32_t& r0, uint32_t& r1,
                                       uint32_t& r2, uint32_t& r3, uint32_t addr) {
    asm volatile("ldmatrix.sync.aligned.m8n8.x4.shared.b16 {%0,%1,%2,%3}, [%4];"
                 : "=r"(r0), "=r"(r1), "=r"(r2), "=r"(r3) : "r"(addr));
}
__device__ __forceinline__ void ldm_x4_t(uint32_t& r0, uint32_t& r1,
                                         uint32_t& r2, uint32_t& r3, uint32_t addr) {
    asm volatile("ldmatrix.sync.aligned.m8n8.x4.trans.shared.b16 {%0,%1,%2,%3}, [%4];"
                 : "=r"(r0), "=r"(r1), "=r"(r2), "=r"(r3) : "r"(addr));
}
__device__ __forceinline__ void mma16816(float* c, uint32_t a0, uint32_t a1,
                                         uint32_t a2, uint32_t a3,
                                         uint32_t b0, uint32_t b1) {
    asm volatile(
        "mma.sync.aligned.m16n8k16.row.col.f32.bf16.bf16.f32 "
        "{%0,%1,%2,%3}, {%4,%5,%6,%7}, {%8,%9}, {%0,%1,%2,%3};"
        : "+f"(c[0]), "+f"(c[1]), "+f"(c[2]), "+f"(c[3])
        : "r"(a0), "r"(a1), "r"(a2), "r"(a3), "r"(b0), "r"(b1));
}
__device__ __forceinline__ uint32_t taddr(uint32_t base, int stride,
                                          int k0, int col0, int lane) {
    int g = lane >> 3, r = lane & 7;
    return base + (uint32_t)((k0 + ((g >> 1) << 3) + r) * stride
                             + (col0 + ((g & 1) << 3)) * 2);
}
__device__ __forceinline__ void split2(float v, __nv_bfloat16& h, __nv_bfloat16& l) {
    h = __float2bfloat16(v);
    l = __float2bfloat16(v - __bfloat162float(h));
}
__device__ __forceinline__ float softplusf(float x) {
    return fmaxf(x, 0.0f) + log1pf(expf(-fabsf(x)));
}

// ---------------------------------------------------------------------------
// HMMA split-bf16 GEMM-NT core: 128x128x64 CTA tile, 3-stage cp.async
// ---------------------------------------------------------------------------
#define KC 64
#define ROWB 144                         // 64 bf16 (128B) + 16B pad; 9 mod 8 = 1
#define TILE_B (128 * ROWB)              // 18432
#define STAGE_B (4 * TILE_B)             // 73728 (Ah, Al, Bh, Bl)
#define NSTAGE 3
#define GEMM_DSMEM (NSTAGE * STAGE_B)    // 221184 B

template <int SPLIT_OUT>
__device__ __forceinline__ void gemm_core(
    const __nv_bfloat16* __restrict__ Ah, const __nv_bfloat16* __restrict__ Al,
    const __nv_bfloat16* __restrict__ Bh, const __nv_bfloat16* __restrict__ Bl,
    const float* __restrict__ bias, float* __restrict__ C,
    __nv_bfloat16* __restrict__ Ch, __nv_bfloat16* __restrict__ Cl, int Mcols) {
    extern __shared__ char dsm[];
    const uint32_t sbase = smem_u32(dsm);

    const int tid = threadIdx.x;
    const int wid = tid >> 5, lane = tid & 31;
    const int warp_m = wid >> 2;
    const int warp_n = wid & 3;
    const int bm = blockIdx.x * 128;
    const int bn = blockIdx.y * 128;

    const int lrow = lane & 15;
    const int lchunk = (lane >> 4) * 16;

    float acc[4][4][4];
#pragma unroll
    for (int i = 0; i < 4; ++i)
#pragma unroll
        for (int j = 0; j < 4; ++j)
#pragma unroll
            for (int q = 0; q < 4; ++q) acc[i][j][q] = 0.0f;

    const int Lrow = tid >> 1;
    const int Lc = (tid & 1) * 4;         // 4 of 8 16B chunks per 128B row
    const int arow = bn + Lrow;
    const int brow = bm + Lrow;

    auto issue_chunk = [&](int c, int stage) {
        const int k0 = c * KC;
        const uint32_t st = sbase + stage * STAGE_B;
        const uint32_t soff = (uint32_t)Lrow * ROWB + Lc * 16;
        const __nv_bfloat16* pa = Ah + (size_t)arow * GK + k0 + Lc * 8;
        const __nv_bfloat16* pl = Al + (size_t)arow * GK + k0 + Lc * 8;
        const __nv_bfloat16* pb = Bh + (size_t)brow * GK + k0 + Lc * 8;
        const __nv_bfloat16* pc = Bl + (size_t)brow * GK + k0 + Lc * 8;
#pragma unroll
        for (int q = 0; q < 4; ++q) {
            cp_async16(st + soff + q * 16, pa + q * 8);
            cp_async16(st + TILE_B + soff + q * 16, pl + q * 8);
            cp_async16(st + 2 * TILE_B + soff + q * 16, pb + q * 8);
            cp_async16(st + 3 * TILE_B + soff + q * 16, pc + q * 8);
        }
        asm volatile("cp.async.commit_group;" ::: "memory");
    };

    issue_chunk(0, 0);
    issue_chunk(1, 1);

    const int NCH = GK / KC;     // 16
    for (int c = 0; c < NCH; ++c) {
        if (c + 1 < NCH) { asm volatile("cp.async.wait_group 1;" ::: "memory"); }
        else             { asm volatile("cp.async.wait_group 0;" ::: "memory"); }
        __syncthreads();

        const uint32_t st = sbase + (c % NSTAGE) * STAGE_B;
        const uint32_t a_base = st + (uint32_t)(warp_m * 64 + lrow) * ROWB + lchunk;
        const uint32_t b_base = st + 2 * TILE_B + (uint32_t)(warp_n * 32 + lrow) * ROWB + lchunk;

#pragma unroll
        for (int s = 0; s < 4; ++s) {
            uint32_t ah[4][4], al[4][4];
#pragma unroll
            for (int i = 0; i < 4; ++i) {
                uint32_t ad = a_base + (uint32_t)i * 16 * ROWB + s * 32;
                ldm_x4(ah[i][0], ah[i][1], ah[i][2], ah[i][3], ad);
                ldm_x4(al[i][0], al[i][1], al[i][2], al[i][3], ad + TILE_B);
            }
            uint32_t bh[2][4], bl[2][4];
#pragma unroll
            for (int j2 = 0; j2 < 2; ++j2) {
                uint32_t bd = b_base + (uint32_t)j2 * 16 * ROWB + s * 32;
                ldm_x4(bh[j2][0], bh[j2][1], bh[j2][2], bh[j2][3], bd);
                ldm_x4(bl[j2][0], bl[j2][1], bl[j2][2], bl[j2][3], bd + TILE_B);
            }
#pragma unroll
            for (int i = 0; i < 4; ++i) {
#pragma unroll
                for (int j = 0; j < 4; ++j) {
                    const int j2 = j >> 1, sel = j & 1;
                    mma16816(acc[i][j], ah[i][0], ah[i][1], ah[i][2], ah[i][3],
                             bh[j2][sel], bh[j2][sel + 2]);
                    mma16816(acc[i][j], al[i][0], al[i][1], al[i][2], al[i][3],
                             bh[j2][sel], bh[j2][sel + 2]);
                    mma16816(acc[i][j], ah[i][0], ah[i][1], ah[i][2], ah[i][3],
                             bl[j2][sel], bl[j2][sel + 2]);
                }
            }
        }
        __syncthreads();
        if (c + 2 < NCH) issue_chunk(c + 2, (c + 2) % NSTAGE);
    }

#pragma unroll
    for (int i = 0; i < 4; ++i) {
#pragma unroll
        for (int j = 0; j < 4; ++j) {
            const int row0 = bn + warp_m * 64 + i * 16 + (lane >> 2);
            const int col = bm + warp_n * 32 + j * 8 + (lane & 3) * 2;
            const float2 bv = *(const float2*)(bias + col);
            float o00 = acc[i][j][0] + bv.x, o01 = acc[i][j][1] + bv.y;
            float o10 = acc[i][j][2] + bv.x, o11 = acc[i][j][3] + bv.y;
            if (SPLIT_OUT) {
                __nv_bfloat16 h0, l0, h1, l1;
                split2(o00, h0, l0); split2(o01, h1, l1);
                *(__nv_bfloat162*)(Ch + (size_t)row0 * Mcols + col) = __nv_bfloat162(h0, h1);
                *(__nv_bfloat162*)(Cl + (size_t)row0 * Mcols + col) = __nv_bfloat162(l0, l1);
                split2(o10, h0, l0); split2(o11, h1, l1);
                *(__nv_bfloat162*)(Ch + (size_t)(row0 + 8) * Mcols + col) = __nv_bfloat162(h0, h1);
                *(__nv_bfloat162*)(Cl + (size_t)(row0 + 8) * Mcols + col) = __nv_bfloat162(l0, l1);
            } else {
                *(float2*)(C + (size_t)row0 * Mcols + col) = make_float2(o00, o01);
                *(float2*)(C + (size_t)(row0 + 8) * Mcols + col) = make_float2(o10, o11);
            }
        }
    }
}

__global__ void __launch_bounds__(256)
gemm_mma_f32(const __nv_bfloat16* Ah, const __nv_bfloat16* Al,
             const __nv_bfloat16* Bh, const __nv_bfloat16* Bl,
             const float* bias, float* C, int Mcols) {
    gemm_core<0>(Ah, Al, Bh, Bl, bias, C, nullptr, nullptr, Mcols);
}
__global__ void __launch_bounds__(256)
gemm_mma_split(const __nv_bfloat16* Ah, const __nv_bfloat16* Al,
               const __nv_bfloat16* Bh, const __nv_bfloat16* Bl,
               const float* bias, __nv_bfloat16* Ch, __nv_bfloat16* Cl, int Mcols) {
    gemm_core<1>(Ah, Al, Bh, Bl, bias, nullptr, Ch, Cl, Mcols);
}

// ---------------------------------------------------------------------------
// phi_mma: qp[b,h,s,f] = softplus( sum_d q[s,d]*rf[d,f] ), split-bf16 out
// grid (32 stile, 2 fchunk, 64 bh), 256 thr. CTA tile: 128s x 128f, K=64.
// ---------------------------------------------------------------------------
#define PH_QS 144
#define PH_RS 272
#define PH_QL (128 * PH_QS)                 // 18432
#define PH_RFH (2 * 128 * PH_QS)            // 36864
#define PH_RFL (PH_RFH + 64 * PH_RS)        // 54272
#define PH_DSMEM (PH_RFL + 64 * PH_RS)      // 71680

__global__ void __launch_bounds__(256)
phi_mma(const __nv_bfloat16* __restrict__ Qh, const __nv_bfloat16* __restrict__ Ql,
        const __nv_bfloat16* __restrict__ RFh, const __nv_bfloat16* __restrict__ RFl,
        __nv_bfloat16* __restrict__ Ph, __nv_bfloat16* __restrict__ Pl) {
    extern __shared__ char dsm[];
    const uint32_t sb = smem_u32(dsm);
    const int tid = threadIdx.x;
    const int wid = tid >> 5, lane = tid & 31;
    const int stile = blockIdx.x, fc = blockIdx.y, bh = blockIdx.z;
    const int b = bh >> 4, h = bh & 15;
    const int s0 = stile * 128;

    {
        const int r = tid >> 1, c0 = (tid & 1) * 4;
        const __nv_bfloat16* ph = Qh + ((size_t)(b * SS + s0 + r)) * DD + h * HD + c0 * 8;
        const __nv_bfloat16* pl = Ql + ((size_t)(b * SS + s0 + r)) * DD + h * HD + c0 * 8;
        const uint32_t so = sb + (uint32_t)r * PH_QS + c0 * 16;
#pragma unroll
        for (int q = 0; q < 4; ++q) {
            cp_async16(so + q * 16, ph + q * 8);
            cp_async16(so + PH_QL + q * 16, pl + q * 8);
        }
    }
    {
        const int r = tid >> 2, c0 = (tid & 3) * 4;
        const __nv_bfloat16* ph = RFh + (size_t)h * HD * FF + (size_t)r * FF + fc * 128 + c0 * 8;
        const __nv_bfloat16* pl = RFl + (size_t)h * HD * FF + (size_t)r * FF + fc * 128 + c0 * 8;
        const uint32_t so = sb + PH_RFH + (uint32_t)r * PH_RS + c0 * 16;
#pragma unroll
        for (int q = 0; q < 4; ++q) {
            cp_async16(so + q * 16, ph + q * 8);
            cp_async16(so + (PH_RFL - PH_RFH) + q * 16, pl + q * 8);
        }
    }
    asm volatile("cp.async.commit_group;" ::: "memory");
    asm volatile("cp.async.wait_group 0;" ::: "memory");
    __syncthreads();

    float acc[16][4];
#pragma unroll
    for (int j = 0; j < 16; ++j)
#pragma unroll
        for (int q = 0; q < 4; ++q) acc[j][q] = 0.0f;

    const int lrow = lane & 15, lch = (lane >> 4) * 16;
    const uint32_t a_base = sb + (uint32_t)(wid * 16 + lrow) * PH_QS + lch;

#pragma unroll
    for (int ks = 0; ks < 4; ++ks) {
        uint32_t ah[4], al[4];
        uint32_t ad = a_base + ks * 32;
        ldm_x4(ah[0], ah[1], ah[2], ah[3], ad);
        ldm_x4(al[0], al[1], al[2], al[3], ad + PH_QL);
#pragma unroll
        for (int ft = 0; ft < 8; ++ft) {
            uint32_t bh4[4], bl4[4];
            uint32_t bd = taddr(sb + PH_RFH, PH_RS, ks * 16, ft * 16, lane);
            ldm_x4_t(bh4[0], bh4[1], bh4[2], bh4[3], bd);
            ldm_x4_t(bl4[0], bl4[1], bl4[2], bl4[3], bd + (PH_RFL - PH_RFH));
#pragma unroll
            for (int sel = 0; sel < 2; ++sel) {
                const int j = ft * 2 + sel;
                mma16816(acc[j], ah[0], ah[1], ah[2], ah[3], bh4[sel], bh4[sel + 2]);
                mma16816(acc[j], al[0], al[1], al[2], al[3], bh4[sel], bh4[sel + 2]);
                mma16816(acc[j], ah[0], ah[1], ah[2], ah[3], bl4[sel], bl4[sel + 2]);
            }
        }
    }

    const int r0 = wid * 16 + (lane >> 2);
#pragma unroll
    for (int j = 0; j < 16; ++j) {
        const int col = fc * 128 + j * 8 + (lane & 3) * 2;
        float s00 = softplusf(acc[j][0]), s01 = softplusf(acc[j][1]);
        float s10 = softplusf(acc[j][2]), s11 = softplusf(acc[j][3]);
        __nv_bfloat16 h0, l0, h1, l1;
        size_t o0 = ((size_t)bh * SS + s0 + r0) * FF + col;
        size_t o1 = ((size_t)bh * SS + s0 + r0 + 8) * FF + col;
        split2(s00, h0, l0); split2(s01, h1, l1);
        *(__nv_bfloat162*)(Ph + o0) = __nv_bfloat162(h0, h1);
        *(__nv_bfloat162*)(Pl + o0) = __nv_bfloat162(l0, l1);
        split2(s10, h0, l0); split2(s11, h1, l1);
        *(__nv_bfloat162*)(Ph + o1) = __nv_bfloat162(h0, h1);
        *(__nv_bfloat162*)(Pl + o1) = __nv_bfloat162(l0, l1);
    }
}

// ---------------------------------------------------------------------------
// kv_mma: kv[f,d] += sum_s kp[s,f]*v[s,d]; ksum folded in via ones column
// (v tile extended to 72 cols: col 64 = 1.0 hi / 0 lo; cols 65-71 = 0).
// grid (8 s-chunk, 16 h, 4 b), 256 thr. CTA: 256f x 64d(+ksum), s-chunk 512.
// ---------------------------------------------------------------------------
#define KV_KS 528                         // 33 mod 8 = 1: conflict-free
#define KV_VS 144                         // 9 mod 8 = 1: conflict-free
#define KV_KH 0
#define KV_KL 16896
#define KV_VH 33792
#define KV_VL (KV_VH + 32 * KV_VS + 32)   // 38432 (+32 slack for dg4 overread)
#define KV_STG (KV_VL + 32 * KV_VS + 32)  // 43072
#define KV_DSMEM (2 * KV_STG)             // 86144

__global__ void __launch_bounds__(256)
kv_mma(const __nv_bfloat16* __restrict__ Kph, const __nv_bfloat16* __restrict__ Kpl,
       const __nv_bfloat16* __restrict__ Vh, const __nv_bfloat16* __restrict__ Vl,
       float* __restrict__ kv, float* __restrict__ ksum) {
    extern __shared__ char dsm[];
    const uint32_t sb = smem_u32(dsm);
    const int tid = threadIdx.x;
    const int wid = tid >> 5, lane = tid & 31;
    const int chunk = blockIdx.x, h = blockIdx.y, b = blockIdx.z;
    const int bh = b * HH + h;
    const int sbase0 = chunk * 512;

    // ones/zeros columns (bytes 128..143 of each V row) — cp.async never
    // writes these; initialize once for both stages.
    if (tid < 64) {
        const int stg = tid >> 5, r = tid & 31;
        const uint32_t bvh = sb + stg * KV_STG + KV_VH + r * KV_VS + 128;
        const uint32_t bvl = sb + stg * KV_STG + KV_VL + r * KV_VS + 128;
        asm volatile("st.shared.v4.b32 [%0], {%1,%2,%3,%4};"
                     :: "r"(bvh), "r"(0x00003F80u), "r"(0u), "r"(0u), "r"(0u));
        asm volatile("st.shared.v4.b32 [%0], {%1,%2,%3,%4};"
                     :: "r"(bvl), "r"(0u), "r"(0u), "r"(0u), "r"(0u));
    }

    auto issue = [&](int t, int stg) {
        const int s0 = sbase0 + t * 32;
        const uint32_t st = sb + stg * KV_STG;
        const int r = tid >> 3;
        {
            const int c0 = (tid & 7) * 4;
            const __nv_bfloat16* ph = Kph + ((size_t)bh * SS + s0 + r) * FF + c0 * 8;
            const __nv_bfloat16* pl = Kpl + ((size_t)bh * SS + s0 + r) * FF + c0 * 8;
            const uint32_t so = st + (uint32_t)r * KV_KS + c0 * 16;
#pragma unroll
            for (int q = 0; q < 4; ++q) {
                cp_async16(so + q * 16, ph + q * 8);
                cp_async16(so + KV_KL + q * 16, pl + q * 8);
            }
        }
        {
            const int c = tid & 7;
            const __nv_bfloat16* ph = Vh + ((size_t)(b * SS + s0 + r)) * DD + h * HD + c * 8;
            const __nv_bfloat16* pl = Vl + ((size_t)(b * SS + s0 + r)) * DD + h * HD + c * 8;
            cp_async16(st + KV_VH + (uint32_t)r * KV_VS + c * 16, ph);
            cp_async16(st + KV_VL + (uint32_t)r * KV_VS + c * 16, pl);
        }
        asm volatile("cp.async.commit_group;" ::: "memory");
    };

    float acc[2][9][4];
#pragma unroll
    for (int i = 0; i < 2; ++i)
#pragma unroll
        for (int j = 0; j < 9; ++j)
#pragma unroll
            for (int q = 0; q < 4; ++q) acc[i][j][q] = 0.0f;

    issue(0, 0);
    for (int t = 0; t < 16; ++t) {
        if (t + 1 < 16) issue(t + 1, (t + 1) & 1);
        if (t + 1 < 16) { asm volatile("cp.async.wait_group 1;" ::: "memory"); }
        else            { asm volatile("cp.async.wait_group 0;" ::: "memory"); }
        __syncthreads();
        const uint32_t st = sb + (t & 1) * KV_STG;

#pragma unroll
        for (int ks = 0; ks < 2; ++ks) {
            uint32_t ah[2][4], al[2][4];
#pragma unroll
            for (int mt = 0; mt < 2; ++mt) {
                uint32_t ad = taddr(st + KV_KH, KV_KS, ks * 16, wid * 32 + mt * 16, lane);
                ldm_x4_t(ah[mt][0], ah[mt][1], ah[mt][2], ah[mt][3], ad);
                ldm_x4_t(al[mt][0], al[mt][1], al[mt][2], al[mt][3], ad + KV_KL);
            }
#pragma unroll
            for (int dg = 0; dg < 5; ++dg) {
                uint32_t bh4[4], bl4[4];
                uint32_t bd = taddr(st + KV_VH, KV_VS, ks * 16, dg * 16, lane);
                ldm_x4_t(bh4[0], bh4[1], bh4[2], bh4[3], bd);
                ldm_x4_t(bl4[0], bl4[1], bl4[2], bl4[3], bd + (KV_VL - KV_VH));
                const int nsel = (dg == 4) ? 1 : 2;
#pragma unroll
                for (int mt = 0; mt < 2; ++mt) {
#pragma unroll
                    for (int sel = 0; sel < 2; ++sel) {
                        if (sel >= nsel) continue;
                        const int j = dg * 2 + sel;
                        mma16816(acc[mt][j], ah[mt][0], ah[mt][1], ah[mt][2], ah[mt][3],
                                 bh4[sel], bh4[sel + 2]);
                        mma16816(acc[mt][j], al[mt][0], al[mt][1], al[mt][2], al[mt][3],
                                 bh4[sel], bh4[sel + 2]);
                        mma16816(acc[mt][j], ah[mt][0], ah[mt][1], ah[mt][2], ah[mt][3],
                                 bl4[sel], bl4[sel + 2]);
                    }
                }
            }
        }
        __syncthreads();
    }

    float* kvp = kv + (size_t)bh * FF * HD;
#pragma unroll
    for (int mt = 0; mt < 2; ++mt) {
        const int f0 = wid * 32 + mt * 16 + (lane >> 2);
#pragma unroll
        for (int j = 0; j < 8; ++j) {
            const int d0 = j * 8 + (lane & 3) * 2;
            atomicAdd(&kvp[f0 * HD + d0],       acc[mt][j][0]);
            atomicAdd(&kvp[f0 * HD + d0 + 1],   acc[mt][j][1]);
            atomicAdd(&kvp[(f0 + 8) * HD + d0],     acc[mt][j][2]);
            atomicAdd(&kvp[(f0 + 8) * HD + d0 + 1], acc[mt][j][3]);
        }
        if ((lane & 3) == 0) {    // col 64 = ksum
            atomicAdd(&ksum[(size_t)bh * FF + f0],     acc[mt][8][0]);
            atomicAdd(&ksum[(size_t)bh * FF + f0 + 8], acc[mt][8][2]);
        }
    }
}

// ---------------------------------------------------------------------------
// split_kvx: pack kv fp32 (64 cols) + ksum (col 64) + zeros (65-71) into
// split-bf16 extended layout [bh*256+f][72].
// ---------------------------------------------------------------------------
__global__ void __launch_bounds__(256)
split_kvx(const float* __restrict__ kv, const float* __restrict__ ksum,
          __nv_bfloat16* __restrict__ kvxh, __nv_bfloat16* __restrict__ kvxl) {
    const int idx = blockIdx.x * 256 + threadIdx.x;    // (bh*256 + f)
    if (idx >= BB * HH * FF) return;
    const float* src = kv + (size_t)idx * HD;
    __nv_bfloat16* dh = kvxh + (size_t)idx * 72;
    __nv_bfloat16* dl = kvxl + (size_t)idx * 72;
    __nv_bfloat16 h, l;
#pragma unroll 8
    for (int c = 0; c < 64; ++c) {
        split2(src[c], h, l);
        dh[c] = h; dl[c] = l;
    }
    split2(ksum[idx], h, l);
    dh[64] = h; dl[64] = l;
#pragma unroll
    for (int c = 65; c < 72; ++c) { dh[c] = __float2bfloat16(0.0f); dl[c] = __float2bfloat16(0.0f); }
}

// ---------------------------------------------------------------------------
// out_mma: y = (qp @ kvx) / (col64 + 1e-8); denom from the same MMA.
// grid (32 stile, 16 h, 4 b), 256 thr. CTA: 128s x 72d, K=F=256.
// ---------------------------------------------------------------------------
#define OM_KVS 144                        // 9 mod 8 = 1: conflict-free
#define OM_KVH 0
#define OM_KVL (256 * OM_KVS)             // 36864
#define OM_Q (2 * 256 * OM_KVS + 64)      // 73792 (+64 slack)
#define OM_QS 80
#define OM_QSTG 20480                     // qh(10240)+ql(10240)
#define OM_DSMEM (OM_Q + 2 * OM_QSTG)     // 114752

__global__ void __launch_bounds__(256)
out_mma(const __nv_bfloat16* __restrict__ Qph, const __nv_bfloat16* __restrict__ Qpl,
        const __nv_bfloat16* __restrict__ KVh, const __nv_bfloat16* __restrict__ KVl,
        __nv_bfloat16* __restrict__ Yh, __nv_bfloat16* __restrict__ Yl) {
    extern __shared__ char dsm[];
    const uint32_t sb = smem_u32(dsm);
    const int tid = threadIdx.x;
    const int wid = tid >> 5, lane = tid & 31;
    const int stile = blockIdx.x, h = blockIdx.y, b = blockIdx.z;
    const int bh = b * HH + h;
    const int s0 = stile * 128;

    auto issue_q = [&](int c) {
        const uint32_t st = sb + OM_Q + (c & 1) * OM_QSTG;
#pragma unroll
        for (int q = 0; q < 2; ++q) {
            const int idx = tid * 2 + q;
            const int r = idx >> 2, cc = idx & 3;
            const __nv_bfloat16* ph = Qph + ((size_t)bh * SS + s0 + r) * FF + c * 32 + cc * 8;
            const __nv_bfloat16* pl = Qpl + ((size_t)bh * SS + s0 + r) * FF + c * 32 + cc * 8;
            cp_async16(st + (uint32_t)r * OM_QS + cc * 16, ph);
            cp_async16(st + 10240 + (uint32_t)r * OM_QS + cc * 16, pl);
        }
        asm volatile("cp.async.commit_group;" ::: "memory");
    };

    // kvx resident load: 256 rows x 144B (9 chunks each), hi + lo
    {
        const __nv_bfloat16* ph = KVh + ((size_t)bh * FF + tid) * 72;
        const __nv_bfloat16* pl = KVl + ((size_t)bh * FF + tid) * 72;
        const uint32_t so = sb + (uint32_t)tid * OM_KVS;
#pragma unroll
        for (int q = 0; q < 9; ++q) {
            cp_async16(so + q * 16, ph + q * 8);
            cp_async16(so + OM_KVL + q * 16, pl + q * 8);
        }
        asm volatile("cp.async.commit_group;" ::: "memory");
    }
    issue_q(0);
    issue_q(1);

    float acc[9][4];
#pragma unroll
    for (int j = 0; j < 9; ++j)
#pragma unroll
        for (int q = 0; q < 4; ++q) acc[j][q] = 0.0f;

    const int lrow = lane & 15, lch = (lane >> 4) * 16;

    for (int c = 0; c < 8; ++c) {
        if (c < 7) { asm volatile("cp.async.wait_group 1;" ::: "memory"); }
        else       { asm volatile("cp.async.wait_group 0;" ::: "memory"); }
        __syncthreads();
        const uint32_t qst = sb + OM_Q + (c & 1) * OM_QSTG;

#pragma unroll
        for (int ks = 0; ks < 2; ++ks) {
            uint32_t ah[4], al[4];
            uint32_t ad = qst + (uint32_t)(wid * 16 + lrow) * OM_QS + lch + ks * 32;
            ldm_x4(ah[0], ah[1], ah[2], ah[3], ad);
            ldm_x4(al[0], al[1], al[2], al[3], ad + 10240);
#pragma unroll
            for (int dg = 0; dg < 5; ++dg) {
                uint32_t bh4[4], bl4[4];
                uint32_t bd = taddr(sb + OM_KVH, OM_KVS, c * 32 + ks * 16, dg * 16, lane);
                ldm_x4_t(bh4[0], bh4[1], bh4[2], bh4[3], bd);
                ldm_x4_t(bl4[0], bl4[1], bl4[2], bl4[3], bd + OM_KVL);
                const int nsel = (dg == 4) ? 1 : 2;
#pragma unroll
                for (int sel = 0; sel < 2; ++sel) {
                    if (sel >= nsel) continue;
                    const int j = dg * 2 + sel;
                    mma16816(acc[j], ah[0], ah[1], ah[2], ah[3], bh4[sel], bh4[sel + 2]);
                    mma16816(acc[j], al[0], al[1], al[2], al[3], bh4[sel], bh4[sel + 2]);
                    mma16816(acc[j], ah[0], ah[1], ah[2], ah[3], bl4[sel], bl4[sel + 2]);
                }
            }
        }
        __syncthreads();
        if (c + 2 < 8) issue_q(c + 2);
    }

    // denominator: col 64 lives in acc[8][0]/acc[8][2] of the quad-leader lane
    const int r0 = wid * 16 + (lane >> 2);
    const float den0 = __shfl_sync(0xffffffffu, acc[8][0], lane & ~3);
    const float den1 = __shfl_sync(0xffffffffu, acc[8][2], lane & ~3);
    const float inv0 = 1.0f / (den0 + 1e-8f);
    const float inv1 = 1.0f / (den1 + 1e-8f);
#pragma unroll
    for (int j = 0; j < 8; ++j) {
        const int col = h * HD + j * 8 + (lane & 3) * 2;
        float o00 = acc[j][0] * inv0, o01 = acc[j][1] * inv0;
        float o10 = acc[j][2] * inv1, o11 = acc[j][3] * inv1;
        __nv_bfloat16 h0, l0, h1, l1;
        size_t off0 = ((size_t)(b * SS + s0 + r0)) * DD + col;
        size_t off1 = ((size_t)(b * SS + s0 + r0 + 8)) * DD + col;
        split2(o00, h0, l0); split2(o01, h1, l1);
        *(__nv_bfloat162*)(Yh + off0) = __nv_bfloat162(h0, h1);
        *(__nv_bfloat162*)(Yl + off0) = __nv_bfloat162(l0, l1);
        split2(o10, h0, l0); split2(o11, h1, l1);
        *(__nv_bfloat162*)(Yh + off1) = __nv_bfloat162(h0, h1);
        *(__nv_bfloat162*)(Yl + off1) = __nv_bfloat162(l0, l1);
    }
}

// ---------------------------------------------------------------------------
// split fp32 -> (bf16 hi, bf16 lo) ; zero
// ---------------------------------------------------------------------------
__global__ void __launch_bounds__(256)
split_bf16(const float* __restrict__ in, __nv_bfloat16* __restrict__ hi,
           __nv_bfloat16* __restrict__ lo, int n) {
    int i = (blockIdx.x * 256 + threadIdx.x) * 4;
    if (i >= n) return;
    float4 v = *(const float4*)(in + i);
    float a[4] = {v.x, v.y, v.z, v.w};
    __nv_bfloat16 h[4], l[4];
#pragma unroll
    for (int j = 0; j < 4; ++j) split2(a[j], h[j], l[j]);
    *(__nv_bfloat162*)(hi + i)     = __nv_bfloat162(h[0], h[1]);
    *(__nv_bfloat162*)(hi + i + 2) = __nv_bfloat162(h[2], h[3]);
    *(__nv_bfloat162*)(lo + i)     = __nv_bfloat162(l[0], l[1]);
    *(__nv_bfloat162*)(lo + i + 2) = __nv_bfloat162(l[2], l[3]);
}
__global__ void zero_kernel(float* __restrict__ p, int n) {
    int i = blockIdx.x * blockDim.x + threadIdx.x;
    if (i < n) p[i] = 0.0f;
}

// ---------------------------------------------------------------------------
// launch
// ---------------------------------------------------------------------------
extern "C" void kernel_launch(void* const* d_in, const int* in_sizes, int n_in,
                              void* d_out, int out_size) {
    const float* x  = (const float*)d_in[0];
    const float* Wq = (const float*)d_in[1];
    const float* bq = (const float*)d_in[2];
    const float* Wk = (const float*)d_in[3];
    const float* bk = (const float*)d_in[4];
    const float* Wv = (const float*)d_in[5];
    const float* bv = (const float*)d_in[6];
    const float* Wo = (const float*)d_in[7];
    const float* bo = (const float*)d_in[8];
    const float* rf = (const float*)d_in[9];
    float* out = (float*)d_out;

    __nv_bfloat16 *pxh, *pxl, *pwh, *pwl, *prfh, *prfl;
    __nv_bfloat16 *pqh, *pql, *pkh, *pkl, *pvh, *pvl, *pyh, *pyl;
    __nv_bfloat16 *pqph, *pqpl, *pkph, *pkpl, *pkvh, *pkvl;
    float *pkv, *pks;
    cudaGetSymbolAddress((void**)&pxh, g_xh);
    cudaGetSymbolAddress((void**)&pxl, g_xl);
    cudaGetSymbolAddress((void**)&pwh, g_wh);
    cudaGetSymbolAddress((void**)&pwl, g_wl);
    cudaGetSymbolAddress((void**)&prfh, g_rfh);
    cudaGetSymbolAddress((void**)&prfl, g_rfl);
    cudaGetSymbolAddress((void**)&pqh, g_qh);
    cudaGetSymbolAddress((void**)&pql, g_ql);
    cudaGetSymbolAddress((void**)&pkh, g_kh);
    cudaGetSymbolAddress((void**)&pkl, g_kl);
    cudaGetSymbolAddress((void**)&pvh, g_vh);
    cudaGetSymbolAddress((void**)&pvl, g_vl);
    cudaGetSymbolAddress((void**)&pyh, g_yh);
    cudaGetSymbolAddress((void**)&pyl, g_yl);
    cudaGetSymbolAddress((void**)&pqph, g_qph);
    cudaGetSymbolAddress((void**)&pqpl, g_qpl);
    cudaGetSymbolAddress((void**)&pkph, g_kph);
    cudaGetSymbolAddress((void**)&pkpl, g_kpl);
    cudaGetSymbolAddress((void**)&pkvh, g_kvh);
    cudaGetSymbolAddress((void**)&pkvl, g_kvl);
    cudaGetSymbolAddress((void**)&pkv, g_kv);
    cudaGetSymbolAddress((void**)&pks, g_ksum);

    cudaFuncSetAttribute(gemm_mma_f32, cudaFuncAttributeMaxDynamicSharedMemorySize, GEMM_DSMEM);
    cudaFuncSetAttribute(gemm_mma_split, cudaFuncAttributeMaxDynamicSharedMemorySize, GEMM_DSMEM);
    cudaFuncSetAttribute(phi_mma, cudaFuncAttributeMaxDynamicSharedMemorySize, PH_DSMEM);
    cudaFuncSetAttribute(kv_mma, cudaFuncAttributeMaxDynamicSharedMemorySize, KV_DSMEM);
    cudaFuncSetAttribute(out_mma, cudaFuncAttributeMaxDynamicSharedMemorySize, OM_DSMEM);

    const int WSZ = DD * DD;

    split_bf16<<<NN * DD / 4 / 256, 256>>>(x, pxh, pxl, NN * DD);
    split_bf16<<<WSZ / 4 / 256, 256>>>(Wq, pwh + 0 * WSZ, pwl + 0 * WSZ, WSZ);
    split_bf16<<<WSZ / 4 / 256, 256>>>(Wk, pwh + 1 * WSZ, pwl + 1 * WSZ, WSZ);
    split_bf16<<<WSZ / 4 / 256, 256>>>(Wv, pwh + 2 * WSZ, pwl + 2 * WSZ, WSZ);
    split_bf16<<<WSZ / 4 / 256, 256>>>(Wo, pwh + 3 * WSZ, pwl + 3 * WSZ, WSZ);
    split_bf16<<<HH * HD * FF / 4 / 256, 256>>>(rf, prfh, prfl, HH * HD * FF);

    dim3 gg(DD / 128, NN / 128);
    gemm_mma_split<<<gg, 256, GEMM_DSMEM>>>(pxh, pxl, pwh + 0 * WSZ, pwl + 0 * WSZ, bq, pqh, pql, DD);
    gemm_mma_split<<<gg, 256, GEMM_DSMEM>>>(pxh, pxl, pwh + 1 * WSZ, pwl + 1 * WSZ, bk, pkh, pkl, DD);
    gemm_mma_split<<<gg, 256, GEMM_DSMEM>>>(pxh, pxl, pwh + 2 * WSZ, pwl + 2 * WSZ, bv, pvh, pvl, DD);

    dim3 pg(SS / 128, 2, BB * HH);
    phi_mma<<<pg, 256, PH_DSMEM>>>(pqh, pql, prfh, prfl, pqph, pqpl);
    phi_mma<<<pg, 256, PH_DSMEM>>>(pkh, pkl, prfh, prfl, pkph, pkpl);

    zero_kernel<<<(BB * HH * FF * HD + 255) / 256, 256>>>(pkv, BB * HH * FF * HD);
    zero_kernel<<<(BB * HH * FF + 255) / 256, 256>>>(pks, BB * HH * FF);

    kv_mma<<<dim3(8, HH, BB), 256, KV_DSMEM>>>(pkph, pkpl, pvh, pvl, pkv, pks);

    split_kvx<<<(BB * HH * FF + 255) / 256, 256>>>(pkv, pks, pkvh, pkvl);

    out_mma<<<dim3(SS / 128, HH, BB), 256, OM_DSMEM>>>(pqph, pqpl, pkvh, pkvl, pyh, pyl);

    gemm_mma_f32<<<gg, 256, GEMM_DSMEM>>>(pyh, pyl, pwh + 3 * WSZ, pwl + 3 * WSZ, bo, out, DD);
}

// round 9
// speedup vs baseline: 1.3184x; 1.3184x over previous
#include <cuda_runtime.h>
#include <cuda_fp16.h>
#include <math.h>
#include <stdint.h>

// ---------------------------------------------------------------------------
// Problem constants
// ---------------------------------------------------------------------------
#define BB 4
#define SS 4096
#define DD 1024
#define HH 16
#define FF 256
#define HD 64
#define NN (BB * SS)          // 16384 rows
#define GK 1024               // GEMM K

// ---------------------------------------------------------------------------
// Scratch (device globals; no allocations allowed)
// A-side operands keep hi+lo (double-fp16 ~22 bits); B-side operands hi only.
// ---------------------------------------------------------------------------
__device__ __half g_xh[NN * DD];
__device__ __half g_xl[NN * DD];
__device__ __half g_wh[4 * DD * DD];        // B-side: hi only
__device__ __half g_rfh[HH * HD * FF];      // B-side: hi only

__device__ __half g_qh[NN * DD];
__device__ __half g_ql[NN * DD];
__device__ __half g_kh[NN * DD];
__device__ __half g_kl[NN * DD];
__device__ __half g_vh[NN * DD];
__device__ __half g_vl[NN * DD];            // written by split-gemm, unused
__device__ __half g_yh[NN * DD];
__device__ __half g_yl[NN * DD];

__device__ __half g_qph[(size_t)BB * HH * SS * FF];
__device__ __half g_qpl[(size_t)BB * HH * SS * FF];
__device__ __half g_kph[(size_t)BB * HH * SS * FF];
__device__ __half g_kpl[(size_t)BB * HH * SS * FF];

__device__ float g_kv[(size_t)BB * HH * FF * HD];     // fp32 (atomics)
__device__ float g_ksum[(size_t)BB * HH * FF];
// extended kv: 72 cols = kv(64) | ksum_hi(64) ksum_lo(65) | zeros(66-71)
__device__ __half g_kvh[(size_t)BB * HH * FF * 72];

// ---------------------------------------------------------------------------
// PTX helpers (base-target: cp.async / ldmatrix / mma.sync)
// ---------------------------------------------------------------------------
__device__ __forceinline__ uint32_t smem_u32(const void* p) {
    return (uint32_t)__cvta_generic_to_shared(p);
}
__device__ __forceinline__ void cp_async16(uint32_t dst, const void* src) {
    asm volatile("cp.async.cg.shared.global [%0], [%1], 16;"
                 :: "r"(dst), "l"(src) : "memory");
}
__device__ __forceinline__ void ldm_x4(uint32_t& r0, uint32_t& r1,
                                       uint32_t& r2, uint32_t& r3, uint32_t addr) {
    asm volatile("ldmatrix.sync.aligned.m8n8.x4.shared.b16 {%0,%1,%2,%3}, [%4];"
                 : "=r"(r0), "=r"(r1), "=r"(r2), "=r"(r3) : "r"(addr));
}
__device__ __forceinline__ void ldm_x4_t(uint32_t& r0, uint32_t& r1,
                                         uint32_t& r2, uint32_t& r3, uint32_t addr) {
    asm volatile("ldmatrix.sync.aligned.m8n8.x4.trans.shared.b16 {%0,%1,%2,%3}, [%4];"
                 : "=r"(r0), "=r"(r1), "=r"(r2), "=r"(r3) : "r"(addr));
}
__device__ __forceinline__ void mma16816(float* c, uint32_t a0, uint32_t a1,
                                         uint32_t a2, uint32_t a3,
                                         uint32_t b0, uint32_t b1) {
    asm volatile(
        "mma.sync.aligned.m16n8k16.row.col.f32.f16.f16.f32 "
        "{%0,%1,%2,%3}, {%4,%5,%6,%7}, {%8,%9}, {%0,%1,%2,%3};"
        : "+f"(c[0]), "+f"(c[1]), "+f"(c[2]), "+f"(c[3])
        : "r"(a0), "r"(a1), "r"(a2), "r"(a3), "r"(b0), "r"(b1));
}
__device__ __forceinline__ uint32_t taddr(uint32_t base, int stride,
                                          int k0, int col0, int lane) {
    int g = lane >> 3, r = lane & 7;
    return base + (uint32_t)((k0 + ((g >> 1) << 3) + r) * stride
                             + (col0 + ((g & 1) << 3)) * 2);
}
__device__ __forceinline__ void split2(float v, __half& h, __half& l) {
    h = __float2half_rn(v);
    l = __float2half_rn(v - __half2float(h));
}
__device__ __forceinline__ float softplusf(float x) {
    return fmaxf(x, 0.0f) + log1pf(expf(-fabsf(x)));
}

// ---------------------------------------------------------------------------
// HMMA 2-pass split-fp16 GEMM-NT: C = A @ B^T + bias, A = Ah+Al, B ~ Bh.
// 128x128x64 CTA tile, 3 smem tiles per stage (Ah, Al, Bh), 3 stages.
// ---------------------------------------------------------------------------
#define KC 64
#define ROWB 144                         // 128B data + 16B pad; 9 mod 8 = 1
#define TILE_B (128 * ROWB)              // 18432
#define STAGE_B (3 * TILE_B)             // 55296
#define NSTAGE 3
#define GEMM_DSMEM (NSTAGE * STAGE_B)    // 165888 B

template <int SPLIT_OUT>
__device__ __forceinline__ void gemm_core(
    const __half* __restrict__ Ah, const __half* __restrict__ Al,
    const __half* __restrict__ Bh,
    const float* __restrict__ bias, float* __restrict__ C,
    __half* __restrict__ Ch, __half* __restrict__ Cl, int Mcols) {
    extern __shared__ char dsm[];
    const uint32_t sbase = smem_u32(dsm);

    const int tid = threadIdx.x;
    const int wid = tid >> 5, lane = tid & 31;
    const int warp_m = wid >> 2;
    const int warp_n = wid & 3;
    const int bm = blockIdx.x * 128;
    const int bn = blockIdx.y * 128;

    const int lrow = lane & 15;
    const int lchunk = (lane >> 4) * 16;

    float acc[4][4][4];
#pragma unroll
    for (int i = 0; i < 4; ++i)
#pragma unroll
        for (int j = 0; j < 4; ++j)
#pragma unroll
            for (int q = 0; q < 4; ++q) acc[i][j][q] = 0.0f;

    const int Lrow = tid >> 1;
    const int Lc = (tid & 1) * 4;
    const int arow = bn + Lrow;
    const int brow = bm + Lrow;

    auto issue_chunk = [&](int c, int stage) {
        const int k0 = c * KC;
        const uint32_t st = sbase + stage * STAGE_B;
        const uint32_t soff = (uint32_t)Lrow * ROWB + Lc * 16;
        const __half* pa = Ah + (size_t)arow * GK + k0 + Lc * 8;
        const __half* pl = Al + (size_t)arow * GK + k0 + Lc * 8;
        const __half* pb = Bh + (size_t)brow * GK + k0 + Lc * 8;
#pragma unroll
        for (int q = 0; q < 4; ++q) {
            cp_async16(st + soff + q * 16, pa + q * 8);
            cp_async16(st + TILE_B + soff + q * 16, pl + q * 8);
            cp_async16(st + 2 * TILE_B + soff + q * 16, pb + q * 8);
        }
        asm volatile("cp.async.commit_group;" ::: "memory");
    };

    issue_chunk(0, 0);
    issue_chunk(1, 1);

    const int NCH = GK / KC;     // 16
    for (int c = 0; c < NCH; ++c) {
        if (c + 1 < NCH) { asm volatile("cp.async.wait_group 1;" ::: "memory"); }
        else             { asm volatile("cp.async.wait_group 0;" ::: "memory"); }
        __syncthreads();

        const uint32_t st = sbase + (c % NSTAGE) * STAGE_B;
        const uint32_t a_base = st + (uint32_t)(warp_m * 64 + lrow) * ROWB + lchunk;
        const uint32_t b_base = st + 2 * TILE_B + (uint32_t)(warp_n * 32 + lrow) * ROWB + lchunk;

#pragma unroll
        for (int s = 0; s < 4; ++s) {
            uint32_t ah[4][4], al[4][4];
#pragma unroll
            for (int i = 0; i < 4; ++i) {
                uint32_t ad = a_base + (uint32_t)i * 16 * ROWB + s * 32;
                ldm_x4(ah[i][0], ah[i][1], ah[i][2], ah[i][3], ad);
                ldm_x4(al[i][0], al[i][1], al[i][2], al[i][3], ad + TILE_B);
            }
            uint32_t bh[2][4];
#pragma unroll
            for (int j2 = 0; j2 < 2; ++j2) {
                uint32_t bd = b_base + (uint32_t)j2 * 16 * ROWB + s * 32;
                ldm_x4(bh[j2][0], bh[j2][1], bh[j2][2], bh[j2][3], bd);
            }
#pragma unroll
            for (int i = 0; i < 4; ++i) {
#pragma unroll
                for (int j = 0; j < 4; ++j) {
                    const int j2 = j >> 1, sel = j & 1;
                    mma16816(acc[i][j], ah[i][0], ah[i][1], ah[i][2], ah[i][3],
                             bh[j2][sel], bh[j2][sel + 2]);
                    mma16816(acc[i][j], al[i][0], al[i][1], al[i][2], al[i][3],
                             bh[j2][sel], bh[j2][sel + 2]);
                }
            }
        }
        __syncthreads();
        if (c + 2 < NCH) issue_chunk(c + 2, (c + 2) % NSTAGE);
    }

#pragma unroll
    for (int i = 0; i < 4; ++i) {
#pragma unroll
        for (int j = 0; j < 4; ++j) {
            const int row0 = bn + warp_m * 64 + i * 16 + (lane >> 2);
            const int col = bm + warp_n * 32 + j * 8 + (lane & 3) * 2;
            const float2 bv = *(const float2*)(bias + col);
            float o00 = acc[i][j][0] + bv.x, o01 = acc[i][j][1] + bv.y;
            float o10 = acc[i][j][2] + bv.x, o11 = acc[i][j][3] + bv.y;
            if (SPLIT_OUT) {
                __half h0, l0, h1, l1;
                split2(o00, h0, l0); split2(o01, h1, l1);
                *(__half2*)(Ch + (size_t)row0 * Mcols + col) = __halves2half2(h0, h1);
                *(__half2*)(Cl + (size_t)row0 * Mcols + col) = __halves2half2(l0, l1);
                split2(o10, h0, l0); split2(o11, h1, l1);
                *(__half2*)(Ch + (size_t)(row0 + 8) * Mcols + col) = __halves2half2(h0, h1);
                *(__half2*)(Cl + (size_t)(row0 + 8) * Mcols + col) = __halves2half2(l0, l1);
            } else {
                *(float2*)(C + (size_t)row0 * Mcols + col) = make_float2(o00, o01);
                *(float2*)(C + (size_t)(row0 + 8) * Mcols + col) = make_float2(o10, o11);
            }
        }
    }
}

__global__ void __launch_bounds__(256)
gemm_mma_f32(const __half* Ah, const __half* Al, const __half* Bh,
             const float* bias, float* C, int Mcols) {
    gemm_core<0>(Ah, Al, Bh, bias, C, nullptr, nullptr, Mcols);
}
__global__ void __launch_bounds__(256)
gemm_mma_split(const __half* Ah, const __half* Al, const __half* Bh,
               const float* bias, __half* Ch, __half* Cl, int Mcols) {
    gemm_core<1>(Ah, Al, Bh, bias, nullptr, Ch, Cl, Mcols);
}

// ---------------------------------------------------------------------------
// phi_mma: qp = softplus(q @ rf), A = q split, B = rf hi only.
// grid (32 stile, 2 fchunk, 64 bh), 256 thr. CTA: 128s x 128f, K=64.
// ---------------------------------------------------------------------------
#define PH_QS 144
#define PH_RS 272
#define PH_QL (128 * PH_QS)                 // 18432
#define PH_RFH (2 * 128 * PH_QS)            // 36864
#define PH_DSMEM (PH_RFH + 64 * PH_RS)      // 54272

__global__ void __launch_bounds__(256)
phi_mma(const __half* __restrict__ Qh, const __half* __restrict__ Ql,
        const __half* __restrict__ RFh,
        __half* __restrict__ Ph, __half* __restrict__ Pl) {
    extern __shared__ char dsm[];
    const uint32_t sb = smem_u32(dsm);
    const int tid = threadIdx.x;
    const int wid = tid >> 5, lane = tid & 31;
    const int stile = blockIdx.x, fc = blockIdx.y, bh = blockIdx.z;
    const int b = bh >> 4, h = bh & 15;
    const int s0 = stile * 128;

    {
        const int r = tid >> 1, c0 = (tid & 1) * 4;
        const __half* ph = Qh + ((size_t)(b * SS + s0 + r)) * DD + h * HD + c0 * 8;
        const __half* pl = Ql + ((size_t)(b * SS + s0 + r)) * DD + h * HD + c0 * 8;
        const uint32_t so = sb + (uint32_t)r * PH_QS + c0 * 16;
#pragma unroll
        for (int q = 0; q < 4; ++q) {
            cp_async16(so + q * 16, ph + q * 8);
            cp_async16(so + PH_QL + q * 16, pl + q * 8);
        }
    }
    {
        const int r = tid >> 2, c0 = (tid & 3) * 4;
        const __half* ph = RFh + (size_t)h * HD * FF + (size_t)r * FF + fc * 128 + c0 * 8;
        const uint32_t so = sb + PH_RFH + (uint32_t)r * PH_RS + c0 * 16;
#pragma unroll
        for (int q = 0; q < 4; ++q) cp_async16(so + q * 16, ph + q * 8);
    }
    asm volatile("cp.async.commit_group;" ::: "memory");
    asm volatile("cp.async.wait_group 0;" ::: "memory");
    __syncthreads();

    float acc[16][4];
#pragma unroll
    for (int j = 0; j < 16; ++j)
#pragma unroll
        for (int q = 0; q < 4; ++q) acc[j][q] = 0.0f;

    const int lrow = lane & 15, lch = (lane >> 4) * 16;
    const uint32_t a_base = sb + (uint32_t)(wid * 16 + lrow) * PH_QS + lch;

#pragma unroll
    for (int ks = 0; ks < 4; ++ks) {
        uint32_t ah[4], al[4];
        uint32_t ad = a_base + ks * 32;
        ldm_x4(ah[0], ah[1], ah[2], ah[3], ad);
        ldm_x4(al[0], al[1], al[2], al[3], ad + PH_QL);
#pragma unroll
        for (int ft = 0; ft < 8; ++ft) {
            uint32_t bh4[4];
            uint32_t bd = taddr(sb + PH_RFH, PH_RS, ks * 16, ft * 16, lane);
            ldm_x4_t(bh4[0], bh4[1], bh4[2], bh4[3], bd);
#pragma unroll
            for (int sel = 0; sel < 2; ++sel) {
                const int j = ft * 2 + sel;
                mma16816(acc[j], ah[0], ah[1], ah[2], ah[3], bh4[sel], bh4[sel + 2]);
                mma16816(acc[j], al[0], al[1], al[2], al[3], bh4[sel], bh4[sel + 2]);
            }
        }
    }

    const int r0 = wid * 16 + (lane >> 2);
#pragma unroll
    for (int j = 0; j < 16; ++j) {
        const int col = fc * 128 + j * 8 + (lane & 3) * 2;
        float s00 = softplusf(acc[j][0]), s01 = softplusf(acc[j][1]);
        float s10 = softplusf(acc[j][2]), s11 = softplusf(acc[j][3]);
        __half h0, l0, h1, l1;
        size_t o0 = ((size_t)bh * SS + s0 + r0) * FF + col;
        size_t o1 = ((size_t)bh * SS + s0 + r0 + 8) * FF + col;
        split2(s00, h0, l0); split2(s01, h1, l1);
        *(__half2*)(Ph + o0) = __halves2half2(h0, h1);
        *(__half2*)(Pl + o0) = __halves2half2(l0, l1);
        split2(s10, h0, l0); split2(s11, h1, l1);
        *(__half2*)(Ph + o1) = __halves2half2(h0, h1);
        *(__half2*)(Pl + o1) = __halves2half2(l0, l1);
    }
}

// ---------------------------------------------------------------------------
// kv_mma: kv[f,d] += sum_s kp[s,f]*v[s,d]; ksum via ones column (col 64 of V).
// A = k' split (trans), B = v hi only. grid (8, 16, 4), 256 thr.
// ---------------------------------------------------------------------------
#define KV_KS 528
#define KV_VS 144
#define KV_KH 0
#define KV_KL 16896
#define KV_VH 33792
#define KV_STG (KV_VH + 32 * KV_VS + 32)  // 38432
#define KV_DSMEM (2 * KV_STG)             // 76864

__global__ void __launch_bounds__(256)
kv_mma(const __half* __restrict__ Kph, const __half* __restrict__ Kpl,
       const __half* __restrict__ Vh,
       float* __restrict__ kv, float* __restrict__ ksum) {
    extern __shared__ char dsm[];
    const uint32_t sb = smem_u32(dsm);
    const int tid = threadIdx.x;
    const int wid = tid >> 5, lane = tid & 31;
    const int chunk = blockIdx.x, h = blockIdx.y, b = blockIdx.z;
    const int bh = b * HH + h;
    const int sbase0 = chunk * 512;

    // ones/zeros columns (bytes 128..143 of each V row), both stages.
    // fp16 1.0 = 0x3C00 in col 64; cols 65-71 zero.
    if (tid < 64) {
        const int stg = tid >> 5, r = tid & 31;
        const uint32_t bvh = sb + stg * KV_STG + KV_VH + r * KV_VS + 128;
        asm volatile("st.shared.v4.b32 [%0], {%1,%2,%3,%4};"
                     :: "r"(bvh), "r"(0x00003C00u), "r"(0u), "r"(0u), "r"(0u));
    }

    auto issue = [&](int t, int stg) {
        const int s0 = sbase0 + t * 32;
        const uint32_t st = sb + stg * KV_STG;
        const int r = tid >> 3;
        {
            const int c0 = (tid & 7) * 4;
            const __half* ph = Kph + ((size_t)bh * SS + s0 + r) * FF + c0 * 8;
            const __half* pl = Kpl + ((size_t)bh * SS + s0 + r) * FF + c0 * 8;
            const uint32_t so = st + (uint32_t)r * KV_KS + c0 * 16;
#pragma unroll
            for (int q = 0; q < 4; ++q) {
                cp_async16(so + q * 16, ph + q * 8);
                cp_async16(so + KV_KL + q * 16, pl + q * 8);
            }
        }
        {
            const int c = tid & 7;
            const __half* ph = Vh + ((size_t)(b * SS + s0 + r)) * DD + h * HD + c * 8;
            cp_async16(st + KV_VH + (uint32_t)r * KV_VS + c * 16, ph);
        }
        asm volatile("cp.async.commit_group;" ::: "memory");
    };

    float acc[2][9][4];
#pragma unroll
    for (int i = 0; i < 2; ++i)
#pragma unroll
        for (int j = 0; j < 9; ++j)
#pragma unroll
            for (int q = 0; q < 4; ++q) acc[i][j][q] = 0.0f;

    issue(0, 0);
    for (int t = 0; t < 16; ++t) {
        if (t + 1 < 16) issue(t + 1, (t + 1) & 1);
        if (t + 1 < 16) { asm volatile("cp.async.wait_group 1;" ::: "memory"); }
        else            { asm volatile("cp.async.wait_group 0;" ::: "memory"); }
        __syncthreads();
        const uint32_t st = sb + (t & 1) * KV_STG;

#pragma unroll
        for (int ks = 0; ks < 2; ++ks) {
            uint32_t ah[2][4], al[2][4];
#pragma unroll
            for (int mt = 0; mt < 2; ++mt) {
                uint32_t ad = taddr(st + KV_KH, KV_KS, ks * 16, wid * 32 + mt * 16, lane);
                ldm_x4_t(ah[mt][0], ah[mt][1], ah[mt][2], ah[mt][3], ad);
                ldm_x4_t(al[mt][0], al[mt][1], al[mt][2], al[mt][3], ad + KV_KL);
            }
#pragma unroll
            for (int dg = 0; dg < 5; ++dg) {
                uint32_t bh4[4];
                uint32_t bd = taddr(st + KV_VH, KV_VS, ks * 16, dg * 16, lane);
                ldm_x4_t(bh4[0], bh4[1], bh4[2], bh4[3], bd);
                const int nsel = (dg == 4) ? 1 : 2;
#pragma unroll
                for (int mt = 0; mt < 2; ++mt) {
#pragma unroll
                    for (int sel = 0; sel < 2; ++sel) {
                        if (sel >= nsel) continue;
                        const int j = dg * 2 + sel;
                        mma16816(acc[mt][j], ah[mt][0], ah[mt][1], ah[mt][2], ah[mt][3],
                                 bh4[sel], bh4[sel + 2]);
                        mma16816(acc[mt][j], al[mt][0], al[mt][1], al[mt][2], al[mt][3],
                                 bh4[sel], bh4[sel + 2]);
                    }
                }
            }
        }
        __syncthreads();
    }

    float* kvp = kv + (size_t)bh * FF * HD;
#pragma unroll
    for (int mt = 0; mt < 2; ++mt) {
        const int f0 = wid * 32 + mt * 16 + (lane >> 2);
#pragma unroll
        for (int j = 0; j < 8; ++j) {
            const int d0 = j * 8 + (lane & 3) * 2;
            atomicAdd(&kvp[f0 * HD + d0],       acc[mt][j][0]);
            atomicAdd(&kvp[f0 * HD + d0 + 1],   acc[mt][j][1]);
            atomicAdd(&kvp[(f0 + 8) * HD + d0],     acc[mt][j][2]);
            atomicAdd(&kvp[(f0 + 8) * HD + d0 + 1], acc[mt][j][3]);
        }
        if ((lane & 3) == 0) {
            atomicAdd(&ksum[(size_t)bh * FF + f0],     acc[mt][8][0]);
            atomicAdd(&ksum[(size_t)bh * FF + f0 + 8], acc[mt][8][2]);
        }
    }
}

// ---------------------------------------------------------------------------
// split_kvx: kv fp32 (64 cols) + ksum split (cols 64/65) + zeros -> fp16 [.][72]
// ---------------------------------------------------------------------------
__global__ void __launch_bounds__(256)
split_kvx(const float* __restrict__ kv, const float* __restrict__ ksum,
          __half* __restrict__ kvxh) {
    const int idx = blockIdx.x * 256 + threadIdx.x;    // (bh*256 + f)
    if (idx >= BB * HH * FF) return;
    const float* src = kv + (size_t)idx * HD;
    __half* dh = kvxh + (size_t)idx * 72;
#pragma unroll 8
    for (int c = 0; c < 64; ++c) dh[c] = __float2half_rn(src[c]);
    __half h, l;
    split2(ksum[idx], h, l);
    dh[64] = h; dh[65] = l;
#pragma unroll
    for (int c = 66; c < 72; ++c) dh[c] = __float2half_rn(0.0f);
}

// ---------------------------------------------------------------------------
// out_mma: y = (qp @ kvx) / (col64+col65 + 1e-8). A = q' split, B = kvx hi.
// grid (32 stile, 16 h, 4 b), 256 thr. CTA: 128s x 72d, K=F=256.
// ---------------------------------------------------------------------------
#define OM_KVS 144
#define OM_KVH 0
#define OM_Q (256 * OM_KVS + 64)          // 36928 (+64 slack for dg4 overread)
#define OM_QS 80
#define OM_QSTG 20480                     // qh(10240)+ql(10240)
#define OM_DSMEM (OM_Q + 2 * OM_QSTG)     // 77888

__global__ void __launch_bounds__(256)
out_mma(const __half* __restrict__ Qph, const __half* __restrict__ Qpl,
        const __half* __restrict__ KVh,
        __half* __restrict__ Yh, __half* __restrict__ Yl) {
    extern __shared__ char dsm[];
    const uint32_t sb = smem_u32(dsm);
    const int tid = threadIdx.x;
    const int wid = tid >> 5, lane = tid & 31;
    const int stile = blockIdx.x, h = blockIdx.y, b = blockIdx.z;
    const int bh = b * HH + h;
    const int s0 = stile * 128;

    auto issue_q = [&](int c) {
        const uint32_t st = sb + OM_Q + (c & 1) * OM_QSTG;
#pragma unroll
        for (int q = 0; q < 2; ++q) {
            const int idx = tid * 2 + q;
            const int r = idx >> 2, cc = idx & 3;
            const __half* ph = Qph + ((size_t)bh * SS + s0 + r) * FF + c * 32 + cc * 8;
            const __half* pl = Qpl + ((size_t)bh * SS + s0 + r) * FF + c * 32 + cc * 8;
            cp_async16(st + (uint32_t)r * OM_QS + cc * 16, ph);
            cp_async16(st + 10240 + (uint32_t)r * OM_QS + cc * 16, pl);
        }
        asm volatile("cp.async.commit_group;" ::: "memory");
    };

    // kvx resident load: 256 rows x 144B (9 chunks each)
    {
        const __half* ph = KVh + ((size_t)bh * FF + tid) * 72;
        const uint32_t so = sb + (uint32_t)tid * OM_KVS;
#pragma unroll
        for (int q = 0; q < 9; ++q) cp_async16(so + q * 16, ph + q * 8);
        asm volatile("cp.async.commit_group;" ::: "memory");
    }
    issue_q(0);
    issue_q(1);

    float acc[9][4];
#pragma unroll
    for (int j = 0; j < 9; ++j)
#pragma unroll
        for (int q = 0; q < 4; ++q) acc[j][q] = 0.0f;

    const int lrow = lane & 15, lch = (lane >> 4) * 16;

    for (int c = 0; c < 8; ++c) {
        if (c < 7) { asm volatile("cp.async.wait_group 1;" ::: "memory"); }
        else       { asm volatile("cp.async.wait_group 0;" ::: "memory"); }
        __syncthreads();
        const uint32_t qst = sb + OM_Q + (c & 1) * OM_QSTG;

#pragma unroll
        for (int ks = 0; ks < 2; ++ks) {
            uint32_t ah[4], al[4];
            uint32_t ad = qst + (uint32_t)(wid * 16 + lrow) * OM_QS + lch + ks * 32;
            ldm_x4(ah[0], ah[1], ah[2], ah[3], ad);
            ldm_x4(al[0], al[1], al[2], al[3], ad + 10240);
#pragma unroll
            for (int dg = 0; dg < 5; ++dg) {
                uint32_t bh4[4];
                uint32_t bd = taddr(sb + OM_KVH, OM_KVS, c * 32 + ks * 16, dg * 16, lane);
                ldm_x4_t(bh4[0], bh4[1], bh4[2], bh4[3], bd);
                const int nsel = (dg == 4) ? 1 : 2;
#pragma unroll
                for (int sel = 0; sel < 2; ++sel) {
                    if (sel >= nsel) continue;
                    const int j = dg * 2 + sel;
                    mma16816(acc[j], ah[0], ah[1], ah[2], ah[3], bh4[sel], bh4[sel + 2]);
                    mma16816(acc[j], al[0], al[1], al[2], al[3], bh4[sel], bh4[sel + 2]);
                }
            }
        }
        __syncthreads();
        if (c + 2 < 8) issue_q(c + 2);
    }

    // denominator: ksum_hi in acc[8][0], ksum_lo in acc[8][1] (quad-leader lane)
    const int r0 = wid * 16 + (lane >> 2);
    const float den0 = __shfl_sync(0xffffffffu, acc[8][0] + acc[8][1], lane & ~3);
    const float den1 = __shfl_sync(0xffffffffu, acc[8][2] + acc[8][3], lane & ~3);
    const float inv0 = 1.0f / (den0 + 1e-8f);
    const float inv1 = 1.0f / (den1 + 1e-8f);
#pragma unroll
    for (int j = 0; j < 8; ++j) {
        const int col = h * HD + j * 8 + (lane & 3) * 2;
        float o00 = acc[j][0] * inv0, o01 = acc[j][1] * inv0;
        float o10 = acc[j][2] * inv1, o11 = acc[j][3] * inv1;
        __half h0, l0, h1, l1;
        size_t off0 = ((size_t)(b * SS + s0 + r0)) * DD + col;
        size_t off1 = ((size_t)(b * SS + s0 + r0 + 8)) * DD + col;
        split2(o00, h0, l0); split2(o01, h1, l1);
        *(__half2*)(Yh + off0) = __halves2half2(h0, h1);
        *(__half2*)(Yl + off0) = __halves2half2(l0, l1);
        split2(o10, h0, l0); split2(o11, h1, l1);
        *(__half2*)(Yh + off1) = __halves2half2(h0, h1);
        *(__half2*)(Yl + off1) = __halves2half2(l0, l1);
    }
}

// ---------------------------------------------------------------------------
// split kernels ; zero
// ---------------------------------------------------------------------------
__global__ void __launch_bounds__(256)
split_pair(const float* __restrict__ in, __half* __restrict__ hi,
           __half* __restrict__ lo, int n) {
    int i = (blockIdx.x * 256 + threadIdx.x) * 4;
    if (i >= n) return;
    float4 v = *(const float4*)(in + i);
    float a[4] = {v.x, v.y, v.z, v.w};
    __half h[4], l[4];
#pragma unroll
    for (int j = 0; j < 4; ++j) split2(a[j], h[j], l[j]);
    *(__half2*)(hi + i)     = __halves2half2(h[0], h[1]);
    *(__half2*)(hi + i + 2) = __halves2half2(h[2], h[3]);
    *(__half2*)(lo + i)     = __halves2half2(l[0], l[1]);
    *(__half2*)(lo + i + 2) = __halves2half2(l[2], l[3]);
}
__global__ void __launch_bounds__(256)
split_hi(const float* __restrict__ in, __half* __restrict__ hi, int n) {
    int i = (blockIdx.x * 256 + threadIdx.x) * 4;
    if (i >= n) return;
    float4 v = *(const float4*)(in + i);
    *(__half2*)(hi + i)     = __halves2half2(__float2half_rn(v.x), __float2half_rn(v.y));
    *(__half2*)(hi + i + 2) = __halves2half2(__float2half_rn(v.z), __float2half_rn(v.w));
}
__global__ void zero_kernel(float* __restrict__ p, int n) {
    int i = blockIdx.x * blockDim.x + threadIdx.x;
    if (i < n) p[i] = 0.0f;
}

// ---------------------------------------------------------------------------
// launch
// ---------------------------------------------------------------------------
extern "C" void kernel_launch(void* const* d_in, const int* in_sizes, int n_in,
                              void* d_out, int out_size) {
    const float* x  = (const float*)d_in[0];
    const float* Wq = (const float*)d_in[1];
    const float* bq = (const float*)d_in[2];
    const float* Wk = (const float*)d_in[3];
    const float* bk = (const float*)d_in[4];
    const float* Wv = (const float*)d_in[5];
    const float* bv = (const float*)d_in[6];
    const float* Wo = (const float*)d_in[7];
    const float* bo = (const float*)d_in[8];
    const float* rf = (const float*)d_in[9];
    float* out = (float*)d_out;

    __half *pxh, *pxl, *pwh, *prfh;
    __half *pqh, *pql, *pkh, *pkl, *pvh, *pvl, *pyh, *pyl;
    __half *pqph, *pqpl, *pkph, *pkpl, *pkvh;
    float *pkv, *pks;
    cudaGetSymbolAddress((void**)&pxh, g_xh);
    cudaGetSymbolAddress((void**)&pxl, g_xl);
    cudaGetSymbolAddress((void**)&pwh, g_wh);
    cudaGetSymbolAddress((void**)&prfh, g_rfh);
    cudaGetSymbolAddress((void**)&pqh, g_qh);
    cudaGetSymbolAddress((void**)&pql, g_ql);
    cudaGetSymbolAddress((void**)&pkh, g_kh);
    cudaGetSymbolAddress((void**)&pkl, g_kl);
    cudaGetSymbolAddress((void**)&pvh, g_vh);
    cudaGetSymbolAddress((void**)&pvl, g_vl);
    cudaGetSymbolAddress((void**)&pyh, g_yh);
    cudaGetSymbolAddress((void**)&pyl, g_yl);
    cudaGetSymbolAddress((void**)&pqph, g_qph);
    cudaGetSymbolAddress((void**)&pqpl, g_qpl);
    cudaGetSymbolAddress((void**)&pkph, g_kph);
    cudaGetSymbolAddress((void**)&pkpl, g_kpl);
    cudaGetSymbolAddress((void**)&pkvh, g_kvh);
    cudaGetSymbolAddress((void**)&pkv, g_kv);
    cudaGetSymbolAddress((void**)&pks, g_ksum);

    cudaFuncSetAttribute(gemm_mma_f32, cudaFuncAttributeMaxDynamicSharedMemorySize, GEMM_DSMEM);
    cudaFuncSetAttribute(gemm_mma_split, cudaFuncAttributeMaxDynamicSharedMemorySize, GEMM_DSMEM);
    cudaFuncSetAttribute(phi_mma, cudaFuncAttributeMaxDynamicSharedMemorySize, PH_DSMEM);
    cudaFuncSetAttribute(kv_mma, cudaFuncAttributeMaxDynamicSharedMemorySize, KV_DSMEM);
    cudaFuncSetAttribute(out_mma, cudaFuncAttributeMaxDynamicSharedMemorySize, OM_DSMEM);

    const int WSZ = DD * DD;

    split_pair<<<NN * DD / 4 / 256, 256>>>(x, pxh, pxl, NN * DD);
    split_hi<<<WSZ / 4 / 256, 256>>>(Wq, pwh + 0 * WSZ, WSZ);
    split_hi<<<WSZ / 4 / 256, 256>>>(Wk, pwh + 1 * WSZ, WSZ);
    split_hi<<<WSZ / 4 / 256, 256>>>(Wv, pwh + 2 * WSZ, WSZ);
    split_hi<<<WSZ / 4 / 256, 256>>>(Wo, pwh + 3 * WSZ, WSZ);
    split_hi<<<HH * HD * FF / 4 / 256, 256>>>(rf, prfh, HH * HD * FF);

    dim3 gg(DD / 128, NN / 128);
    gemm_mma_split<<<gg, 256, GEMM_DSMEM>>>(pxh, pxl, pwh + 0 * WSZ, bq, pqh, pql, DD);
    gemm_mma_split<<<gg, 256, GEMM_DSMEM>>>(pxh, pxl, pwh + 1 * WSZ, bk, pkh, pkl, DD);
    gemm_mma_split<<<gg, 256, GEMM_DSMEM>>>(pxh, pxl, pwh + 2 * WSZ, bv, pvh, pvl, DD);

    dim3 pg(SS / 128, 2, BB * HH);
    phi_mma<<<pg, 256, PH_DSMEM>>>(pqh, pql, prfh, pqph, pqpl);
    phi_mma<<<pg, 256, PH_DSMEM>>>(pkh, pkl, prfh, pkph, pkpl);

    zero_kernel<<<(BB * HH * FF * HD + 255) / 256, 256>>>(pkv, BB * HH * FF * HD);
    zero_kernel<<<(BB * HH * FF + 255) / 256, 256>>>(pks, BB * HH * FF);

    kv_mma<<<dim3(8, HH, BB), 256, KV_DSMEM>>>(pkph, pkpl, pvh, pkv, pks);

    split_kvx<<<(BB * HH * FF + 255) / 256, 256>>>(pkv, pks, pkvh);

    out_mma<<<dim3(SS / 128, HH, BB), 256, OM_DSMEM>>>(pqph, pqpl, pkvh, pyh, pyl);

    gemm_mma_f32<<<gg, 256, GEMM_DSMEM>>>(pyh, pyl, pwh + 3 * WSZ, bo, out, DD);
}

// round 10
// speedup vs baseline: 1.4199x; 1.0770x over previous
#include <cuda_runtime.h>
#include <cuda_fp16.h>
#include <math.h>
#include <stdint.h>

// ---------------------------------------------------------------------------
// Problem constants
// ---------------------------------------------------------------------------
#define BB 4
#define SS 4096
#define DD 1024
#define HH 16
#define FF 256
#define HD 64
#define NN (BB * SS)          // 16384 rows
#define GK 1024               // GEMM K

// ---------------------------------------------------------------------------
// Scratch (device globals; no allocations allowed)
// A-side operands keep hi+lo (double-fp16 ~22 bits); B-side operands hi only.
// ---------------------------------------------------------------------------
__device__ __half g_xh[NN * DD];
__device__ __half g_xl[NN * DD];
__device__ __half g_wh[4 * DD * DD];        // B-side: hi only
__device__ __half g_rfh[HH * HD * FF];      // B-side: hi only

__device__ __half g_qh[NN * DD];
__device__ __half g_ql[NN * DD];
__device__ __half g_kh[NN * DD];
__device__ __half g_kl[NN * DD];
__device__ __half g_vh[NN * DD];
__device__ __half g_vl[NN * DD];            // written by split-gemm, unused
__device__ __half g_yh[NN * DD];
__device__ __half g_yl[NN * DD];

__device__ __half g_qph[(size_t)BB * HH * SS * FF];
__device__ __half g_qpl[(size_t)BB * HH * SS * FF];
__device__ __half g_kph[(size_t)BB * HH * SS * FF];
__device__ __half g_kpl[(size_t)BB * HH * SS * FF];

__device__ float g_kv[(size_t)BB * HH * FF * HD];     // fp32 (atomics)
__device__ float g_ksum[(size_t)BB * HH * FF];
// extended kv: 72 cols = kv(64) | ksum_hi(64) ksum_lo(65) | zeros(66-71)
__device__ __half g_kvh[(size_t)BB * HH * FF * 72];

// ---------------------------------------------------------------------------
// PTX helpers (base-target: cp.async / ldmatrix / mma.sync)
// ---------------------------------------------------------------------------
__device__ __forceinline__ uint32_t smem_u32(const void* p) {
    return (uint32_t)__cvta_generic_to_shared(p);
}
__device__ __forceinline__ void cp_async16(uint32_t dst, const void* src) {
    asm volatile("cp.async.cg.shared.global [%0], [%1], 16;"
                 :: "r"(dst), "l"(src) : "memory");
}
__device__ __forceinline__ void ldm_x4(uint32_t& r0, uint32_t& r1,
                                       uint32_t& r2, uint32_t& r3, uint32_t addr) {
    asm volatile("ldmatrix.sync.aligned.m8n8.x4.shared.b16 {%0,%1,%2,%3}, [%4];"
                 : "=r"(r0), "=r"(r1), "=r"(r2), "=r"(r3) : "r"(addr));
}
__device__ __forceinline__ void ldm_x4_t(uint32_t& r0, uint32_t& r1,
                                         uint32_t& r2, uint32_t& r3, uint32_t addr) {
    asm volatile("ldmatrix.sync.aligned.m8n8.x4.trans.shared.b16 {%0,%1,%2,%3}, [%4];"
                 : "=r"(r0), "=r"(r1), "=r"(r2), "=r"(r3) : "r"(addr));
}
__device__ __forceinline__ void mma16816(float* c, uint32_t a0, uint32_t a1,
                                         uint32_t a2, uint32_t a3,
                                         uint32_t b0, uint32_t b1) {
    asm volatile(
        "mma.sync.aligned.m16n8k16.row.col.f32.f16.f16.f32 "
        "{%0,%1,%2,%3}, {%4,%5,%6,%7}, {%8,%9}, {%0,%1,%2,%3};"
        : "+f"(c[0]), "+f"(c[1]), "+f"(c[2]), "+f"(c[3])
        : "r"(a0), "r"(a1), "r"(a2), "r"(a3), "r"(b0), "r"(b1));
}
__device__ __forceinline__ uint32_t taddr(uint32_t base, int stride,
                                          int k0, int col0, int lane) {
    int g = lane >> 3, r = lane & 7;
    return base + (uint32_t)((k0 + ((g >> 1) << 3) + r) * stride
                             + (col0 + ((g & 1) << 3)) * 2);
}
__device__ __forceinline__ void split2(float v, __half& h, __half& l) {
    h = __float2half_rn(v);
    l = __float2half_rn(v - __half2float(h));
}
__device__ __forceinline__ float softplusf(float x) {
    return fmaxf(x, 0.0f) + log1pf(expf(-fabsf(x)));
}

// ---------------------------------------------------------------------------
// HMMA 2-pass split-fp16 GEMM-NT: C = A @ B^T + bias, A = Ah+Al, B ~ Bh.
// 128x128x64 CTA tile, 3 smem tiles per stage (Ah, Al, Bh), 2 stages
// -> 110.6 KB smem -> 2 CTAs/SM (16 warps) to hide HMMA/ldmatrix latency.
// ---------------------------------------------------------------------------
#define KC 64
#define ROWB 144                         // 128B data + 16B pad; 9 mod 8 = 1
#define TILE_B (128 * ROWB)              // 18432
#define STAGE_B (3 * TILE_B)             // 55296
#define NSTAGE 2
#define GEMM_DSMEM (NSTAGE * STAGE_B)    // 110592 B

template <int SPLIT_OUT>
__device__ __forceinline__ void gemm_core(
    const __half* __restrict__ Ah, const __half* __restrict__ Al,
    const __half* __restrict__ Bh,
    const float* __restrict__ bias, float* __restrict__ C,
    __half* __restrict__ Ch, __half* __restrict__ Cl, int Mcols) {
    extern __shared__ char dsm[];
    const uint32_t sbase = smem_u32(dsm);

    const int tid = threadIdx.x;
    const int wid = tid >> 5, lane = tid & 31;
    const int warp_m = wid >> 2;
    const int warp_n = wid & 3;
    const int bm = blockIdx.x * 128;
    const int bn = blockIdx.y * 128;

    const int lrow = lane & 15;
    const int lchunk = (lane >> 4) * 16;

    float acc[4][4][4];
#pragma unroll
    for (int i = 0; i < 4; ++i)
#pragma unroll
        for (int j = 0; j < 4; ++j)
#pragma unroll
            for (int q = 0; q < 4; ++q) acc[i][j][q] = 0.0f;

    const int Lrow = tid >> 1;
    const int Lc = (tid & 1) * 4;
    const int arow = bn + Lrow;
    const int brow = bm + Lrow;

    auto issue_chunk = [&](int c, int stage) {
        const int k0 = c * KC;
        const uint32_t st = sbase + stage * STAGE_B;
        const uint32_t soff = (uint32_t)Lrow * ROWB + Lc * 16;
        const __half* pa = Ah + (size_t)arow * GK + k0 + Lc * 8;
        const __half* pl = Al + (size_t)arow * GK + k0 + Lc * 8;
        const __half* pb = Bh + (size_t)brow * GK + k0 + Lc * 8;
#pragma unroll
        for (int q = 0; q < 4; ++q) {
            cp_async16(st + soff + q * 16, pa + q * 8);
            cp_async16(st + TILE_B + soff + q * 16, pl + q * 8);
            cp_async16(st + 2 * TILE_B + soff + q * 16, pb + q * 8);
        }
        asm volatile("cp.async.commit_group;" ::: "memory");
    };

    issue_chunk(0, 0);
    issue_chunk(1, 1);

    const int NCH = GK / KC;     // 16
    for (int c = 0; c < NCH; ++c) {
        if (c + 1 < NCH) { asm volatile("cp.async.wait_group 1;" ::: "memory"); }
        else             { asm volatile("cp.async.wait_group 0;" ::: "memory"); }
        __syncthreads();

        const uint32_t st = sbase + (c % NSTAGE) * STAGE_B;
        const uint32_t a_base = st + (uint32_t)(warp_m * 64 + lrow) * ROWB + lchunk;
        const uint32_t b_base = st + 2 * TILE_B + (uint32_t)(warp_n * 32 + lrow) * ROWB + lchunk;

#pragma unroll
        for (int s = 0; s < 4; ++s) {
            uint32_t ah[4][4], al[4][4];
#pragma unroll
            for (int i = 0; i < 4; ++i) {
                uint32_t ad = a_base + (uint32_t)i * 16 * ROWB + s * 32;
                ldm_x4(ah[i][0], ah[i][1], ah[i][2], ah[i][3], ad);
                ldm_x4(al[i][0], al[i][1], al[i][2], al[i][3], ad + TILE_B);
            }
            uint32_t bh[2][4];
#pragma unroll
            for (int j2 = 0; j2 < 2; ++j2) {
                uint32_t bd = b_base + (uint32_t)j2 * 16 * ROWB + s * 32;
                ldm_x4(bh[j2][0], bh[j2][1], bh[j2][2], bh[j2][3], bd);
            }
#pragma unroll
            for (int i = 0; i < 4; ++i) {
#pragma unroll
                for (int j = 0; j < 4; ++j) {
                    const int j2 = j >> 1, sel = j & 1;
                    mma16816(acc[i][j], ah[i][0], ah[i][1], ah[i][2], ah[i][3],
                             bh[j2][sel], bh[j2][sel + 2]);
                    mma16816(acc[i][j], al[i][0], al[i][1], al[i][2], al[i][3],
                             bh[j2][sel], bh[j2][sel + 2]);
                }
            }
        }
        __syncthreads();
        if (c + 2 < NCH) issue_chunk(c + 2, (c + 2) % NSTAGE);
    }

#pragma unroll
    for (int i = 0; i < 4; ++i) {
#pragma unroll
        for (int j = 0; j < 4; ++j) {
            const int row0 = bn + warp_m * 64 + i * 16 + (lane >> 2);
            const int col = bm + warp_n * 32 + j * 8 + (lane & 3) * 2;
            const float2 bv = *(const float2*)(bias + col);
            float o00 = acc[i][j][0] + bv.x, o01 = acc[i][j][1] + bv.y;
            float o10 = acc[i][j][2] + bv.x, o11 = acc[i][j][3] + bv.y;
            if (SPLIT_OUT) {
                __half h0, l0, h1, l1;
                split2(o00, h0, l0); split2(o01, h1, l1);
                *(__half2*)(Ch + (size_t)row0 * Mcols + col) = __halves2half2(h0, h1);
                *(__half2*)(Cl + (size_t)row0 * Mcols + col) = __halves2half2(l0, l1);
                split2(o10, h0, l0); split2(o11, h1, l1);
                *(__half2*)(Ch + (size_t)(row0 + 8) * Mcols + col) = __halves2half2(h0, h1);
                *(__half2*)(Cl + (size_t)(row0 + 8) * Mcols + col) = __halves2half2(l0, l1);
            } else {
                *(float2*)(C + (size_t)row0 * Mcols + col) = make_float2(o00, o01);
                *(float2*)(C + (size_t)(row0 + 8) * Mcols + col) = make_float2(o10, o11);
            }
        }
    }
}

__global__ void __launch_bounds__(256, 2)
gemm_mma_f32(const __half* Ah, const __half* Al, const __half* Bh,
             const float* bias, float* C, int Mcols) {
    gemm_core<0>(Ah, Al, Bh, bias, C, nullptr, nullptr, Mcols);
}
__global__ void __launch_bounds__(256, 2)
gemm_mma_split(const __half* Ah, const __half* Al, const __half* Bh,
               const float* bias, __half* Ch, __half* Cl, int Mcols) {
    gemm_core<1>(Ah, Al, Bh, bias, nullptr, Ch, Cl, Mcols);
}

// ---------------------------------------------------------------------------
// phi_mma: qp = softplus(q @ rf), A = q split, B = rf hi only.
// grid (32 stile, 2 fchunk, 64 bh), 256 thr. CTA: 128s x 128f, K=64.
// ---------------------------------------------------------------------------
#define PH_QS 144
#define PH_RS 272
#define PH_QL (128 * PH_QS)                 // 18432
#define PH_RFH (2 * 128 * PH_QS)            // 36864
#define PH_DSMEM (PH_RFH + 64 * PH_RS)      // 54272

__global__ void __launch_bounds__(256)
phi_mma(const __half* __restrict__ Qh, const __half* __restrict__ Ql,
        const __half* __restrict__ RFh,
        __half* __restrict__ Ph, __half* __restrict__ Pl) {
    extern __shared__ char dsm[];
    const uint32_t sb = smem_u32(dsm);
    const int tid = threadIdx.x;
    const int wid = tid >> 5, lane = tid & 31;
    const int stile = blockIdx.x, fc = blockIdx.y, bh = blockIdx.z;
    const int b = bh >> 4, h = bh & 15;
    const int s0 = stile * 128;

    {
        const int r = tid >> 1, c0 = (tid & 1) * 4;
        const __half* ph = Qh + ((size_t)(b * SS + s0 + r)) * DD + h * HD + c0 * 8;
        const __half* pl = Ql + ((size_t)(b * SS + s0 + r)) * DD + h * HD + c0 * 8;
        const uint32_t so = sb + (uint32_t)r * PH_QS + c0 * 16;
#pragma unroll
        for (int q = 0; q < 4; ++q) {
            cp_async16(so + q * 16, ph + q * 8);
            cp_async16(so + PH_QL + q * 16, pl + q * 8);
        }
    }
    {
        const int r = tid >> 2, c0 = (tid & 3) * 4;
        const __half* ph = RFh + (size_t)h * HD * FF + (size_t)r * FF + fc * 128 + c0 * 8;
        const uint32_t so = sb + PH_RFH + (uint32_t)r * PH_RS + c0 * 16;
#pragma unroll
        for (int q = 0; q < 4; ++q) cp_async16(so + q * 16, ph + q * 8);
    }
    asm volatile("cp.async.commit_group;" ::: "memory");
    asm volatile("cp.async.wait_group 0;" ::: "memory");
    __syncthreads();

    float acc[16][4];
#pragma unroll
    for (int j = 0; j < 16; ++j)
#pragma unroll
        for (int q = 0; q < 4; ++q) acc[j][q] = 0.0f;

    const int lrow = lane & 15, lch = (lane >> 4) * 16;
    const uint32_t a_base = sb + (uint32_t)(wid * 16 + lrow) * PH_QS + lch;

#pragma unroll
    for (int ks = 0; ks < 4; ++ks) {
        uint32_t ah[4], al[4];
        uint32_t ad = a_base + ks * 32;
        ldm_x4(ah[0], ah[1], ah[2], ah[3], ad);
        ldm_x4(al[0], al[1], al[2], al[3], ad + PH_QL);
#pragma unroll
        for (int ft = 0; ft < 8; ++ft) {
            uint32_t bh4[4];
            uint32_t bd = taddr(sb + PH_RFH, PH_RS, ks * 16, ft * 16, lane);
            ldm_x4_t(bh4[0], bh4[1], bh4[2], bh4[3], bd);
#pragma unroll
            for (int sel = 0; sel < 2; ++sel) {
                const int j = ft * 2 + sel;
                mma16816(acc[j], ah[0], ah[1], ah[2], ah[3], bh4[sel], bh4[sel + 2]);
                mma16816(acc[j], al[0], al[1], al[2], al[3], bh4[sel], bh4[sel + 2]);
            }
        }
    }

    const int r0 = wid * 16 + (lane >> 2);
#pragma unroll
    for (int j = 0; j < 16; ++j) {
        const int col = fc * 128 + j * 8 + (lane & 3) * 2;
        float s00 = softplusf(acc[j][0]), s01 = softplusf(acc[j][1]);
        float s10 = softplusf(acc[j][2]), s11 = softplusf(acc[j][3]);
        __half h0, l0, h1, l1;
        size_t o0 = ((size_t)bh * SS + s0 + r0) * FF + col;
        size_t o1 = ((size_t)bh * SS + s0 + r0 + 8) * FF + col;
        split2(s00, h0, l0); split2(s01, h1, l1);
        *(__half2*)(Ph + o0) = __halves2half2(h0, h1);
        *(__half2*)(Pl + o0) = __halves2half2(l0, l1);
        split2(s10, h0, l0); split2(s11, h1, l1);
        *(__half2*)(Ph + o1) = __halves2half2(h0, h1);
        *(__half2*)(Pl + o1) = __halves2half2(l0, l1);
    }
}

// ---------------------------------------------------------------------------
// kv_mma: kv[f,d] += sum_s kp[s,f]*v[s,d]; ksum via ones column (col 64 of V).
// A = k' split (trans), B = v hi only. grid (8, 16, 4), 256 thr.
// ---------------------------------------------------------------------------
#define KV_KS 528
#define KV_VS 144
#define KV_KH 0
#define KV_KL 16896
#define KV_VH 33792
#define KV_STG (KV_VH + 32 * KV_VS + 32)  // 38432
#define KV_DSMEM (2 * KV_STG)             // 76864

__global__ void __launch_bounds__(256)
kv_mma(const __half* __restrict__ Kph, const __half* __restrict__ Kpl,
       const __half* __restrict__ Vh,
       float* __restrict__ kv, float* __restrict__ ksum) {
    extern __shared__ char dsm[];
    const uint32_t sb = smem_u32(dsm);
    const int tid = threadIdx.x;
    const int wid = tid >> 5, lane = tid & 31;
    const int chunk = blockIdx.x, h = blockIdx.y, b = blockIdx.z;
    const int bh = b * HH + h;
    const int sbase0 = chunk * 512;

    if (tid < 64) {
        const int stg = tid >> 5, r = tid & 31;
        const uint32_t bvh = sb + stg * KV_STG + KV_VH + r * KV_VS + 128;
        asm volatile("st.shared.v4.b32 [%0], {%1,%2,%3,%4};"
                     :: "r"(bvh), "r"(0x00003C00u), "r"(0u), "r"(0u), "r"(0u));
    }

    auto issue = [&](int t, int stg) {
        const int s0 = sbase0 + t * 32;
        const uint32_t st = sb + stg * KV_STG;
        const int r = tid >> 3;
        {
            const int c0 = (tid & 7) * 4;
            const __half* ph = Kph + ((size_t)bh * SS + s0 + r) * FF + c0 * 8;
            const __half* pl = Kpl + ((size_t)bh * SS + s0 + r) * FF + c0 * 8;
            const uint32_t so = st + (uint32_t)r * KV_KS + c0 * 16;
#pragma unroll
            for (int q = 0; q < 4; ++q) {
                cp_async16(so + q * 16, ph + q * 8);
                cp_async16(so + KV_KL + q * 16, pl + q * 8);
            }
        }
        {
            const int c = tid & 7;
            const __half* ph = Vh + ((size_t)(b * SS + s0 + r)) * DD + h * HD + c * 8;
            cp_async16(st + KV_VH + (uint32_t)r * KV_VS + c * 16, ph);
        }
        asm volatile("cp.async.commit_group;" ::: "memory");
    };

    float acc[2][9][4];
#pragma unroll
    for (int i = 0; i < 2; ++i)
#pragma unroll
        for (int j = 0; j < 9; ++j)
#pragma unroll
            for (int q = 0; q < 4; ++q) acc[i][j][q] = 0.0f;

    issue(0, 0);
    for (int t = 0; t < 16; ++t) {
        if (t + 1 < 16) issue(t + 1, (t + 1) & 1);
        if (t + 1 < 16) { asm volatile("cp.async.wait_group 1;" ::: "memory"); }
        else            { asm volatile("cp.async.wait_group 0;" ::: "memory"); }
        __syncthreads();
        const uint32_t st = sb + (t & 1) * KV_STG;

#pragma unroll
        for (int ks = 0; ks < 2; ++ks) {
            uint32_t ah[2][4], al[2][4];
#pragma unroll
            for (int mt = 0; mt < 2; ++mt) {
                uint32_t ad = taddr(st + KV_KH, KV_KS, ks * 16, wid * 32 + mt * 16, lane);
                ldm_x4_t(ah[mt][0], ah[mt][1], ah[mt][2], ah[mt][3], ad);
                ldm_x4_t(al[mt][0], al[mt][1], al[mt][2], al[mt][3], ad + KV_KL);
            }
#pragma unroll
            for (int dg = 0; dg < 5; ++dg) {
                uint32_t bh4[4];
                uint32_t bd = taddr(st + KV_VH, KV_VS, ks * 16, dg * 16, lane);
                ldm_x4_t(bh4[0], bh4[1], bh4[2], bh4[3], bd);
                const int nsel = (dg == 4) ? 1 : 2;
#pragma unroll
                for (int mt = 0; mt < 2; ++mt) {
#pragma unroll
                    for (int sel = 0; sel < 2; ++sel) {
                        if (sel >= nsel) continue;
                        const int j = dg * 2 + sel;
                        mma16816(acc[mt][j], ah[mt][0], ah[mt][1], ah[mt][2], ah[mt][3],
                                 bh4[sel], bh4[sel + 2]);
                        mma16816(acc[mt][j], al[mt][0], al[mt][1], al[mt][2], al[mt][3],
                                 bh4[sel], bh4[sel + 2]);
                    }
                }
            }
        }
        __syncthreads();
    }

    float* kvp = kv + (size_t)bh * FF * HD;
#pragma unroll
    for (int mt = 0; mt < 2; ++mt) {
        const int f0 = wid * 32 + mt * 16 + (lane >> 2);
#pragma unroll
        for (int j = 0; j < 8; ++j) {
            const int d0 = j * 8 + (lane & 3) * 2;
            atomicAdd(&kvp[f0 * HD + d0],       acc[mt][j][0]);
            atomicAdd(&kvp[f0 * HD + d0 + 1],   acc[mt][j][1]);
            atomicAdd(&kvp[(f0 + 8) * HD + d0],     acc[mt][j][2]);
            atomicAdd(&kvp[(f0 + 8) * HD + d0 + 1], acc[mt][j][3]);
        }
        if ((lane & 3) == 0) {
            atomicAdd(&ksum[(size_t)bh * FF + f0],     acc[mt][8][0]);
            atomicAdd(&ksum[(size_t)bh * FF + f0 + 8], acc[mt][8][2]);
        }
    }
}

// ---------------------------------------------------------------------------
// split_kvx: kv fp32 (64 cols) + ksum split (cols 64/65) + zeros -> fp16 [.][72]
// ---------------------------------------------------------------------------
__global__ void __launch_bounds__(256)
split_kvx(const float* __restrict__ kv, const float* __restrict__ ksum,
          __half* __restrict__ kvxh) {
    const int idx = blockIdx.x * 256 + threadIdx.x;    // (bh*256 + f)
    if (idx >= BB * HH * FF) return;
    const float* src = kv + (size_t)idx * HD;
    __half* dh = kvxh + (size_t)idx * 72;
#pragma unroll 8
    for (int c = 0; c < 64; ++c) dh[c] = __float2half_rn(src[c]);
    __half h, l;
    split2(ksum[idx], h, l);
    dh[64] = h; dh[65] = l;
#pragma unroll
    for (int c = 66; c < 72; ++c) dh[c] = __float2half_rn(0.0f);
}

// ---------------------------------------------------------------------------
// out_mma: y = (qp @ kvx) / (col64+col65 + 1e-8). A = q' split, B = kvx hi.
// grid (32 stile, 16 h, 4 b), 256 thr. CTA: 128s x 72d, K=F=256.
// ---------------------------------------------------------------------------
#define OM_KVS 144
#define OM_KVH 0
#define OM_Q (256 * OM_KVS + 64)          // 36928 (+64 slack for dg4 overread)
#define OM_QS 80
#define OM_QSTG 20480                     // qh(10240)+ql(10240)
#define OM_DSMEM (OM_Q + 2 * OM_QSTG)     // 77888

__global__ void __launch_bounds__(256)
out_mma(const __half* __restrict__ Qph, const __half* __restrict__ Qpl,
        const __half* __restrict__ KVh,
        __half* __restrict__ Yh, __half* __restrict__ Yl) {
    extern __shared__ char dsm[];
    const uint32_t sb = smem_u32(dsm);
    const int tid = threadIdx.x;
    const int wid = tid >> 5, lane = tid & 31;
    const int stile = blockIdx.x, h = blockIdx.y, b = blockIdx.z;
    const int bh = b * HH + h;
    const int s0 = stile * 128;

    auto issue_q = [&](int c) {
        const uint32_t st = sb + OM_Q + (c & 1) * OM_QSTG;
#pragma unroll
        for (int q = 0; q < 2; ++q) {
            const int idx = tid * 2 + q;
            const int r = idx >> 2, cc = idx & 3;
            const __half* ph = Qph + ((size_t)bh * SS + s0 + r) * FF + c * 32 + cc * 8;
            const __half* pl = Qpl + ((size_t)bh * SS + s0 + r) * FF + c * 32 + cc * 8;
            cp_async16(st + (uint32_t)r * OM_QS + cc * 16, ph);
            cp_async16(st + 10240 + (uint32_t)r * OM_QS + cc * 16, pl);
        }
        asm volatile("cp.async.commit_group;" ::: "memory");
    };

    {
        const __half* ph = KVh + ((size_t)bh * FF + tid) * 72;
        const uint32_t so = sb + (uint32_t)tid * OM_KVS;
#pragma unroll
        for (int q = 0; q < 9; ++q) cp_async16(so + q * 16, ph + q * 8);
        asm volatile("cp.async.commit_group;" ::: "memory");
    }
    issue_q(0);
    issue_q(1);

    float acc[9][4];
#pragma unroll
    for (int j = 0; j < 9; ++j)
#pragma unroll
        for (int q = 0; q < 4; ++q) acc[j][q] = 0.0f;

    const int lrow = lane & 15, lch = (lane >> 4) * 16;

    for (int c = 0; c < 8; ++c) {
        if (c < 7) { asm volatile("cp.async.wait_group 1;" ::: "memory"); }
        else       { asm volatile("cp.async.wait_group 0;" ::: "memory"); }
        __syncthreads();
        const uint32_t qst = sb + OM_Q + (c & 1) * OM_QSTG;

#pragma unroll
        for (int ks = 0; ks < 2; ++ks) {
            uint32_t ah[4], al[4];
            uint32_t ad = qst + (uint32_t)(wid * 16 + lrow) * OM_QS + lch + ks * 32;
            ldm_x4(ah[0], ah[1], ah[2], ah[3], ad);
            ldm_x4(al[0], al[1], al[2], al[3], ad + 10240);
#pragma unroll
            for (int dg = 0; dg < 5; ++dg) {
                uint32_t bh4[4];
                uint32_t bd = taddr(sb + OM_KVH, OM_KVS, c * 32 + ks * 16, dg * 16, lane);
                ldm_x4_t(bh4[0], bh4[1], bh4[2], bh4[3], bd);
                const int nsel = (dg == 4) ? 1 : 2;
#pragma unroll
                for (int sel = 0; sel < 2; ++sel) {
                    if (sel >= nsel) continue;
                    const int j = dg * 2 + sel;
                    mma16816(acc[j], ah[0], ah[1], ah[2], ah[3], bh4[sel], bh4[sel + 2]);
                    mma16816(acc[j], al[0], al[1], al[2], al[3], bh4[sel], bh4[sel + 2]);
                }
            }
        }
        __syncthreads();
        if (c + 2 < 8) issue_q(c + 2);
    }

    const int r0 = wid * 16 + (lane >> 2);
    const float den0 = __shfl_sync(0xffffffffu, acc[8][0] + acc[8][1], lane & ~3);
    const float den1 = __shfl_sync(0xffffffffu, acc[8][2] + acc[8][3], lane & ~3);
    const float inv0 = 1.0f / (den0 + 1e-8f);
    const float inv1 = 1.0f / (den1 + 1e-8f);
#pragma unroll
    for (int j = 0; j < 8; ++j) {
        const int col = h * HD + j * 8 + (lane & 3) * 2;
        float o00 = acc[j][0] * inv0, o01 = acc[j][1] * inv0;
        float o10 = acc[j][2] * inv1, o11 = acc[j][3] * inv1;
        __half h0, l0, h1, l1;
        size_t off0 = ((size_t)(b * SS + s0 + r0)) * DD + col;
        size_t off1 = ((size_t)(b * SS + s0 + r0 + 8)) * DD + col;
        split2(o00, h0, l0); split2(o01, h1, l1);
        *(__half2*)(Yh + off0) = __halves2half2(h0, h1);
        *(__half2*)(Yl + off0) = __halves2half2(l0, l1);
        split2(o10, h0, l0); split2(o11, h1, l1);
        *(__half2*)(Yh + off1) = __halves2half2(h0, h1);
        *(__half2*)(Yl + off1) = __halves2half2(l0, l1);
    }
}

// ---------------------------------------------------------------------------
// split kernels ; zero
// ---------------------------------------------------------------------------
__global__ void __launch_bounds__(256)
split_pair(const float* __restrict__ in, __half* __restrict__ hi,
           __half* __restrict__ lo, int n) {
    int i = (blockIdx.x * 256 + threadIdx.x) * 4;
    if (i >= n) return;
    float4 v = *(const float4*)(in + i);
    float a[4] = {v.x, v.y, v.z, v.w};
    __half h[4], l[4];
#pragma unroll
    for (int j = 0; j < 4; ++j) split2(a[j], h[j], l[j]);
    *(__half2*)(hi + i)     = __halves2half2(h[0], h[1]);
    *(__half2*)(hi + i + 2) = __halves2half2(h[2], h[3]);
    *(__half2*)(lo + i)     = __halves2half2(l[0], l[1]);
    *(__half2*)(lo + i + 2) = __halves2half2(l[2], l[3]);
}
__global__ void __launch_bounds__(256)
split_hi(const float* __restrict__ in, __half* __restrict__ hi, int n) {
    int i = (blockIdx.x * 256 + threadIdx.x) * 4;
    if (i >= n) return;
    float4 v = *(const float4*)(in + i);
    *(__half2*)(hi + i)     = __halves2half2(__float2half_rn(v.x), __float2half_rn(v.y));
    *(__half2*)(hi + i + 2) = __halves2half2(__float2half_rn(v.z), __float2half_rn(v.w));
}
__global__ void zero_kernel(float* __restrict__ p, int n) {
    int i = blockIdx.x * blockDim.x + threadIdx.x;
    if (i < n) p[i] = 0.0f;
}

// ---------------------------------------------------------------------------
// launch
// ---------------------------------------------------------------------------
extern "C" void kernel_launch(void* const* d_in, const int* in_sizes, int n_in,
                              void* d_out, int out_size) {
    const float* x  = (const float*)d_in[0];
    const float* Wq = (const float*)d_in[1];
    const float* bq = (const float*)d_in[2];
    const float* Wk = (const float*)d_in[3];
    const float* bk = (const float*)d_in[4];
    const float* Wv = (const float*)d_in[5];
    const float* bv = (const float*)d_in[6];
    const float* Wo = (const float*)d_in[7];
    const float* bo = (const float*)d_in[8];
    const float* rf = (const float*)d_in[9];
    float* out = (float*)d_out;

    __half *pxh, *pxl, *pwh, *prfh;
    __half *pqh, *pql, *pkh, *pkl, *pvh, *pvl, *pyh, *pyl;
    __half *pqph, *pqpl, *pkph, *pkpl, *pkvh;
    float *pkv, *pks;
    cudaGetSymbolAddress((void**)&pxh, g_xh);
    cudaGetSymbolAddress((void**)&pxl, g_xl);
    cudaGetSymbolAddress((void**)&pwh, g_wh);
    cudaGetSymbolAddress((void**)&prfh, g_rfh);
    cudaGetSymbolAddress((void**)&pqh, g_qh);
    cudaGetSymbolAddress((void**)&pql, g_ql);
    cudaGetSymbolAddress((void**)&pkh, g_kh);
    cudaGetSymbolAddress((void**)&pkl, g_kl);
    cudaGetSymbolAddress((void**)&pvh, g_vh);
    cudaGetSymbolAddress((void**)&pvl, g_vl);
    cudaGetSymbolAddress((void**)&pyh, g_yh);
    cudaGetSymbolAddress((void**)&pyl, g_yl);
    cudaGetSymbolAddress((void**)&pqph, g_qph);
    cudaGetSymbolAddress((void**)&pqpl, g_qpl);
    cudaGetSymbolAddress((void**)&pkph, g_kph);
    cudaGetSymbolAddress((void**)&pkpl, g_kpl);
    cudaGetSymbolAddress((void**)&pkvh, g_kvh);
    cudaGetSymbolAddress((void**)&pkv, g_kv);
    cudaGetSymbolAddress((void**)&pks, g_ksum);

    cudaFuncSetAttribute(gemm_mma_f32, cudaFuncAttributeMaxDynamicSharedMemorySize, GEMM_DSMEM);
    cudaFuncSetAttribute(gemm_mma_split, cudaFuncAttributeMaxDynamicSharedMemorySize, GEMM_DSMEM);
    cudaFuncSetAttribute(phi_mma, cudaFuncAttributeMaxDynamicSharedMemorySize, PH_DSMEM);
    cudaFuncSetAttribute(kv_mma, cudaFuncAttributeMaxDynamicSharedMemorySize, KV_DSMEM);
    cudaFuncSetAttribute(out_mma, cudaFuncAttributeMaxDynamicSharedMemorySize, OM_DSMEM);

    const int WSZ = DD * DD;

    split_pair<<<NN * DD / 4 / 256, 256>>>(x, pxh, pxl, NN * DD);
    split_hi<<<WSZ / 4 / 256, 256>>>(Wq, pwh + 0 * WSZ, WSZ);
    split_hi<<<WSZ / 4 / 256, 256>>>(Wk, pwh + 1 * WSZ, WSZ);
    split_hi<<<WSZ / 4 / 256, 256>>>(Wv, pwh + 2 * WSZ, WSZ);
    split_hi<<<WSZ / 4 / 256, 256>>>(Wo, pwh + 3 * WSZ, WSZ);
    split_hi<<<HH * HD * FF / 4 / 256, 256>>>(rf, prfh, HH * HD * FF);

    dim3 gg(DD / 128, NN / 128);
    gemm_mma_split<<<gg, 256, GEMM_DSMEM>>>(pxh, pxl, pwh + 0 * WSZ, bq, pqh, pql, DD);
    gemm_mma_split<<<gg, 256, GEMM_DSMEM>>>(pxh, pxl, pwh + 1 * WSZ, bk, pkh, pkl, DD);
    gemm_mma_split<<<gg, 256, GEMM_DSMEM>>>(pxh, pxl, pwh + 2 * WSZ, bv, pvh, pvl, DD);

    dim3 pg(SS / 128, 2, BB * HH);
    phi_mma<<<pg, 256, PH_DSMEM>>>(pqh, pql, prfh, pqph, pqpl);
    phi_mma<<<pg, 256, PH_DSMEM>>>(pkh, pkl, prfh, pkph, pkpl);

    zero_kernel<<<(BB * HH * FF * HD + 255) / 256, 256>>>(pkv, BB * HH * FF * HD);
    zero_kernel<<<(BB * HH * FF + 255) / 256, 256>>>(pks, BB * HH * FF);

    kv_mma<<<dim3(8, HH, BB), 256, KV_DSMEM>>>(pkph, pkpl, pvh, pkv, pks);

    split_kvx<<<(BB * HH * FF + 255) / 256, 256>>>(pkv, pks, pkvh);

    out_mma<<<dim3(SS / 128, HH, BB), 256, OM_DSMEM>>>(pqph, pqpl, pkvh, pyh, pyl);

    gemm_mma_f32<<<gg, 256, GEMM_DSMEM>>>(pyh, pyl, pwh + 3 * WSZ, bo, out, DD);
}

// round 12
// speedup vs baseline: 2.4000x; 1.6902x over previous
#include <cuda_runtime.h>
#include <cuda_fp16.h>
#include <math.h>
#include <stdint.h>

// ---------------------------------------------------------------------------
// Problem constants
// ---------------------------------------------------------------------------
#define BB 4
#define SS 4096
#define DD 1024
#define HH 16
#define FF 256
#define HD 64
#define NN (BB * SS)          // 16384 rows
#define GK 1024               // GEMM K

// ---------------------------------------------------------------------------
// Scratch (device globals; no allocations allowed). Pure fp16 operands;
// only kv/ksum accumulate in fp32 (atomics), ksum re-split into kvx cols 64/65.
// ---------------------------------------------------------------------------
__device__ __half g_xh[NN * DD];
__device__ __half g_wh[4 * DD * DD];
__device__ __half g_rfh[HH * HD * FF];

__device__ __half g_qh[NN * DD];
__device__ __half g_kh[NN * DD];
__device__ __half g_vh[NN * DD];
__device__ __half g_yh[NN * DD];

__device__ __half g_qph[(size_t)BB * HH * SS * FF];
__device__ __half g_kph[(size_t)BB * HH * SS * FF];

__device__ float g_kv[(size_t)BB * HH * FF * HD];     // fp32 (atomics)
__device__ float g_ksum[(size_t)BB * HH * FF];
// extended kv: 72 cols = kv(64) | ksum_hi(64) ksum_lo(65) | zeros(66-71)
__device__ __half g_kvh[(size_t)BB * HH * FF * 72];

// ---------------------------------------------------------------------------
// PTX helpers (base-target: cp.async / ldmatrix / mma.sync)
// ---------------------------------------------------------------------------
__device__ __forceinline__ uint32_t smem_u32(const void* p) {
    return (uint32_t)__cvta_generic_to_shared(p);
}
__device__ __forceinline__ void cp_async16(uint32_t dst, const void* src) {
    asm volatile("cp.async.cg.shared.global [%0], [%1], 16;"
                 :: "r"(dst), "l"(src) : "memory");
}
__device__ __forceinline__ void ldm_x4(uint32_t& r0, uint32_t& r1,
                                       uint32_t& r2, uint32_t& r3, uint32_t addr) {
    asm volatile("ldmatrix.sync.aligned.m8n8.x4.shared.b16 {%0,%1,%2,%3}, [%4];"
                 : "=r"(r0), "=r"(r1), "=r"(r2), "=r"(r3) : "r"(addr));
}
__device__ __forceinline__ void ldm_x4_t(uint32_t& r0, uint32_t& r1,
                                         uint32_t& r2, uint32_t& r3, uint32_t addr) {
    asm volatile("ldmatrix.sync.aligned.m8n8.x4.trans.shared.b16 {%0,%1,%2,%3}, [%4];"
                 : "=r"(r0), "=r"(r1), "=r"(r2), "=r"(r3) : "r"(addr));
}
__device__ __forceinline__ void mma16816(float* c, uint32_t a0, uint32_t a1,
                                         uint32_t a2, uint32_t a3,
                                         uint32_t b0, uint32_t b1) {
    asm volatile(
        "mma.sync.aligned.m16n8k16.row.col.f32.f16.f16.f32 "
        "{%0,%1,%2,%3}, {%4,%5,%6,%7}, {%8,%9}, {%0,%1,%2,%3};"
        : "+f"(c[0]), "+f"(c[1]), "+f"(c[2]), "+f"(c[3])
        : "r"(a0), "r"(a1), "r"(a2), "r"(a3), "r"(b0), "r"(b1));
}
__device__ __forceinline__ uint32_t taddr(uint32_t base, int stride,
                                          int k0, int col0, int lane) {
    int g = lane >> 3, r = lane & 7;
    return base + (uint32_t)((k0 + ((g >> 1) << 3) + r) * stride
                             + (col0 + ((g & 1) << 3)) * 2);
}
__device__ __forceinline__ void split2(float v, __half& h, __half& l) {
    h = __float2half_rn(v);
    l = __float2half_rn(v - __half2float(h));
}
__device__ __forceinline__ float softplusf(float x) {
    return fmaxf(x, 0.0f) + log1pf(expf(-fabsf(x)));
}

// ---------------------------------------------------------------------------
// HMMA single-pass fp16 GEMM-NT: C = A @ B^T + bias.
// 128x128x64 CTA tile, 2 smem tiles per stage (A, B), 3 stages
// -> 110.6 KB smem -> 2 CTAs/SM, deeper prefetch.
// ---------------------------------------------------------------------------
#define KC 64
#define ROWB 144                         // 128B data + 16B pad; 9 mod 8 = 1
#define TILE_B (128 * ROWB)              // 18432
#define STAGE_B (2 * TILE_B)             // 36864 (A, B)
#define NSTAGE 3
#define GEMM_DSMEM (NSTAGE * STAGE_B)    // 110592 B

template <int HALF_OUT>
__device__ __forceinline__ void gemm_core(
    const __half* __restrict__ A, const __half* __restrict__ B,
    const float* __restrict__ bias, float* __restrict__ C,
    __half* __restrict__ Ch, int Mcols) {
    extern __shared__ char dsm[];
    const uint32_t sbase = smem_u32(dsm);

    const int tid = threadIdx.x;
    const int wid = tid >> 5, lane = tid & 31;
    const int warp_m = wid >> 2;
    const int warp_n = wid & 3;
    const int bm = blockIdx.x * 128;
    const int bn = blockIdx.y * 128;

    const int lrow = lane & 15;
    const int lchunk = (lane >> 4) * 16;

    float acc[4][4][4];
#pragma unroll
    for (int i = 0; i < 4; ++i)
#pragma unroll
        for (int j = 0; j < 4; ++j)
#pragma unroll
            for (int q = 0; q < 4; ++q) acc[i][j][q] = 0.0f;

    const int Lrow = tid >> 1;
    const int Lc = (tid & 1) * 4;
    const int arow = bn + Lrow;
    const int brow = bm + Lrow;

    auto issue_chunk = [&](int c, int stage) {
        const int k0 = c * KC;
        const uint32_t st = sbase + stage * STAGE_B;
        const uint32_t soff = (uint32_t)Lrow * ROWB + Lc * 16;
        const __half* pa = A + (size_t)arow * GK + k0 + Lc * 8;
        const __half* pb = B + (size_t)brow * GK + k0 + Lc * 8;
#pragma unroll
        for (int q = 0; q < 4; ++q) {
            cp_async16(st + soff + q * 16, pa + q * 8);
            cp_async16(st + TILE_B + soff + q * 16, pb + q * 8);
        }
        asm volatile("cp.async.commit_group;" ::: "memory");
    };

    issue_chunk(0, 0);
    issue_chunk(1, 1);

    const int NCH = GK / KC;     // 16
    for (int c = 0; c < NCH; ++c) {
        if (c + 1 < NCH) { asm volatile("cp.async.wait_group 1;" ::: "memory"); }
        else             { asm volatile("cp.async.wait_group 0;" ::: "memory"); }
        __syncthreads();

        const uint32_t st = sbase + (c % NSTAGE) * STAGE_B;
        const uint32_t a_base = st + (uint32_t)(warp_m * 64 + lrow) * ROWB + lchunk;
        const uint32_t b_base = st + TILE_B + (uint32_t)(warp_n * 32 + lrow) * ROWB + lchunk;

#pragma unroll
        for (int s = 0; s < 4; ++s) {
            uint32_t ah[4][4];
#pragma unroll
            for (int i = 0; i < 4; ++i) {
                uint32_t ad = a_base + (uint32_t)i * 16 * ROWB + s * 32;
                ldm_x4(ah[i][0], ah[i][1], ah[i][2], ah[i][3], ad);
            }
            uint32_t bh[2][4];
#pragma unroll
            for (int j2 = 0; j2 < 2; ++j2) {
                uint32_t bd = b_base + (uint32_t)j2 * 16 * ROWB + s * 32;
                ldm_x4(bh[j2][0], bh[j2][1], bh[j2][2], bh[j2][3], bd);
            }
#pragma unroll
            for (int i = 0; i < 4; ++i) {
#pragma unroll
                for (int j = 0; j < 4; ++j) {
                    const int j2 = j >> 1, sel = j & 1;
                    mma16816(acc[i][j], ah[i][0], ah[i][1], ah[i][2], ah[i][3],
                             bh[j2][sel], bh[j2][sel + 2]);
                }
            }
        }
        __syncthreads();
        if (c + 2 < NCH) issue_chunk(c + 2, (c + 2) % NSTAGE);
    }

#pragma unroll
    for (int i = 0; i < 4; ++i) {
#pragma unroll
        for (int j = 0; j < 4; ++j) {
            const int row0 = bn + warp_m * 64 + i * 16 + (lane >> 2);
            const int col = bm + warp_n * 32 + j * 8 + (lane & 3) * 2;
            const float2 bv = *(const float2*)(bias + col);
            float o00 = acc[i][j][0] + bv.x, o01 = acc[i][j][1] + bv.y;
            float o10 = acc[i][j][2] + bv.x, o11 = acc[i][j][3] + bv.y;
            if (HALF_OUT) {
                *(__half2*)(Ch + (size_t)row0 * Mcols + col) =
                    __halves2half2(__float2half_rn(o00), __float2half_rn(o01));
                *(__half2*)(Ch + (size_t)(row0 + 8) * Mcols + col) =
                    __halves2half2(__float2half_rn(o10), __float2half_rn(o11));
            } else {
                *(float2*)(C + (size_t)row0 * Mcols + col) = make_float2(o00, o01);
                *(float2*)(C + (size_t)(row0 + 8) * Mcols + col) = make_float2(o10, o11);
            }
        }
    }
}

__global__ void __launch_bounds__(256, 2)
gemm_mma_f32(const __half* A, const __half* B,
             const float* bias, float* C, int Mcols) {
    gemm_core<0>(A, B, bias, C, nullptr, Mcols);
}
__global__ void __launch_bounds__(256, 2)
gemm_mma_h(const __half* A, const __half* B,
           const float* bias, __half* Ch, int Mcols) {
    gemm_core<1>(A, B, bias, nullptr, Ch, Mcols);
}

// ---------------------------------------------------------------------------
// phi_mma: qp = softplus(q @ rf), fp16 in/out.
// grid (32 stile, 2 fchunk, 64 bh), 256 thr. CTA: 128s x 128f, K=64.
// ---------------------------------------------------------------------------
#define PH_QS 144
#define PH_RS 272
#define PH_RFH (128 * PH_QS)                // 18432
#define PH_DSMEM (PH_RFH + 64 * PH_RS)      // 35840

__global__ void __launch_bounds__(256)
phi_mma(const __half* __restrict__ Qh, const __half* __restrict__ RFh,
        __half* __restrict__ Ph) {
    extern __shared__ char dsm[];
    const uint32_t sb = smem_u32(dsm);
    const int tid = threadIdx.x;
    const int wid = tid >> 5, lane = tid & 31;
    const int stile = blockIdx.x, fc = blockIdx.y, bh = blockIdx.z;
    const int b = bh >> 4, h = bh & 15;
    const int s0 = stile * 128;

    {
        const int r = tid >> 1, c0 = (tid & 1) * 4;
        const __half* ph = Qh + ((size_t)(b * SS + s0 + r)) * DD + h * HD + c0 * 8;
        const uint32_t so = sb + (uint32_t)r * PH_QS + c0 * 16;
#pragma unroll
        for (int q = 0; q < 4; ++q) cp_async16(so + q * 16, ph + q * 8);
    }
    {
        const int r = tid >> 2, c0 = (tid & 3) * 4;
        const __half* ph = RFh + (size_t)h * HD * FF + (size_t)r * FF + fc * 128 + c0 * 8;
        const uint32_t so = sb + PH_RFH + (uint32_t)r * PH_RS + c0 * 16;
#pragma unroll
        for (int q = 0; q < 4; ++q) cp_async16(so + q * 16, ph + q * 8);
    }
    asm volatile("cp.async.commit_group;" ::: "memory");
    asm volatile("cp.async.wait_group 0;" ::: "memory");
    __syncthreads();

    float acc[16][4];
#pragma unroll
    for (int j = 0; j < 16; ++j)
#pragma unroll
        for (int q = 0; q < 4; ++q) acc[j][q] = 0.0f;

    const int lrow = lane & 15, lch = (lane >> 4) * 16;
    const uint32_t a_base = sb + (uint32_t)(wid * 16 + lrow) * PH_QS + lch;

#pragma unroll
    for (int ks = 0; ks < 4; ++ks) {
        uint32_t ah[4];
        ldm_x4(ah[0], ah[1], ah[2], ah[3], a_base + ks * 32);
#pragma unroll
        for (int ft = 0; ft < 8; ++ft) {
            uint32_t bh4[4];
            uint32_t bd = taddr(sb + PH_RFH, PH_RS, ks * 16, ft * 16, lane);
            ldm_x4_t(bh4[0], bh4[1], bh4[2], bh4[3], bd);
#pragma unroll
            for (int sel = 0; sel < 2; ++sel) {
                const int j = ft * 2 + sel;
                mma16816(acc[j], ah[0], ah[1], ah[2], ah[3], bh4[sel], bh4[sel + 2]);
            }
        }
    }

    const int r0 = wid * 16 + (lane >> 2);
#pragma unroll
    for (int j = 0; j < 16; ++j) {
        const int col = fc * 128 + j * 8 + (lane & 3) * 2;
        float s00 = softplusf(acc[j][0]), s01 = softplusf(acc[j][1]);
        float s10 = softplusf(acc[j][2]), s11 = softplusf(acc[j][3]);
        size_t o0 = ((size_t)bh * SS + s0 + r0) * FF + col;
        size_t o1 = ((size_t)bh * SS + s0 + r0 + 8) * FF + col;
        *(__half2*)(Ph + o0) = __halves2half2(__float2half_rn(s00), __float2half_rn(s01));
        *(__half2*)(Ph + o1) = __halves2half2(__float2half_rn(s10), __float2half_rn(s11));
    }
}

// ---------------------------------------------------------------------------
// kv_mma: kv[f,d] += sum_s kp[s,f]*v[s,d]; ksum via ones column (col 64 of V).
// fp16 in, fp32 atomics out. grid (8, 16, 4), 256 thr.
// ---------------------------------------------------------------------------
#define KV_KS 528
#define KV_VS 144
#define KV_KH 0
#define KV_VH 16896
#define KV_STG (KV_VH + 32 * KV_VS + 32)  // 21536
#define KV_DSMEM (2 * KV_STG)             // 43072

__global__ void __launch_bounds__(256)
kv_mma(const __half* __restrict__ Kph, const __half* __restrict__ Vh,
       float* __restrict__ kv, float* __restrict__ ksum) {
    extern __shared__ char dsm[];
    const uint32_t sb = smem_u32(dsm);
    const int tid = threadIdx.x;
    const int wid = tid >> 5, lane = tid & 31;
    const int chunk = blockIdx.x, h = blockIdx.y, b = blockIdx.z;
    const int bh = b * HH + h;
    const int sbase0 = chunk * 512;

    // ones column (col 64 = fp16 1.0) + zeros (65-71), both stages
    if (tid < 64) {
        const int stg = tid >> 5, r = tid & 31;
        const uint32_t bvh = sb + stg * KV_STG + KV_VH + r * KV_VS + 128;
        asm volatile("st.shared.v4.b32 [%0], {%1,%2,%3,%4};"
                     :: "r"(bvh), "r"(0x00003C00u), "r"(0u), "r"(0u), "r"(0u));
    }

    auto issue = [&](int t, int stg) {
        const int s0 = sbase0 + t * 32;
        const uint32_t st = sb + stg * KV_STG;
        const int r = tid >> 3;
        {
            const int c0 = (tid & 7) * 4;
            const __half* ph = Kph + ((size_t)bh * SS + s0 + r) * FF + c0 * 8;
            const uint32_t so = st + (uint32_t)r * KV_KS + c0 * 16;
#pragma unroll
            for (int q = 0; q < 4; ++q) cp_async16(so + q * 16, ph + q * 8);
        }
        {
            const int c = tid & 7;
            const __half* ph = Vh + ((size_t)(b * SS + s0 + r)) * DD + h * HD + c * 8;
            cp_async16(st + KV_VH + (uint32_t)r * KV_VS + c * 16, ph);
        }
        asm volatile("cp.async.commit_group;" ::: "memory");
    };

    float acc[2][9][4];
#pragma unroll
    for (int i = 0; i < 2; ++i)
#pragma unroll
        for (int j = 0; j < 9; ++j)
#pragma unroll
            for (int q = 0; q < 4; ++q) acc[i][j][q] = 0.0f;

    issue(0, 0);
    for (int t = 0; t < 16; ++t) {
        if (t + 1 < 16) issue(t + 1, (t + 1) & 1);
        if (t + 1 < 16) { asm volatile("cp.async.wait_group 1;" ::: "memory"); }
        else            { asm volatile("cp.async.wait_group 0;" ::: "memory"); }
        __syncthreads();
        const uint32_t st = sb + (t & 1) * KV_STG;

#pragma unroll
        for (int ks = 0; ks < 2; ++ks) {
            uint32_t ah[2][4];
#pragma unroll
            for (int mt = 0; mt < 2; ++mt) {
                uint32_t ad = taddr(st + KV_KH, KV_KS, ks * 16, wid * 32 + mt * 16, lane);
                ldm_x4_t(ah[mt][0], ah[mt][1], ah[mt][2], ah[mt][3], ad);
            }
#pragma unroll
            for (int dg = 0; dg < 5; ++dg) {
                uint32_t bh4[4];
                uint32_t bd = taddr(st + KV_VH, KV_VS, ks * 16, dg * 16, lane);
                ldm_x4_t(bh4[0], bh4[1], bh4[2], bh4[3], bd);
                const int nsel = (dg == 4) ? 1 : 2;
#pragma unroll
                for (int mt = 0; mt < 2; ++mt) {
#pragma unroll
                    for (int sel = 0; sel < 2; ++sel) {
                        if (sel >= nsel) continue;
                        const int j = dg * 2 + sel;
                        mma16816(acc[mt][j], ah[mt][0], ah[mt][1], ah[mt][2], ah[mt][3],
                                 bh4[sel], bh4[sel + 2]);
                    }
                }
            }
        }
        __syncthreads();
    }

    float* kvp = kv + (size_t)bh * FF * HD;
#pragma unroll
    for (int mt = 0; mt < 2; ++mt) {
        const int f0 = wid * 32 + mt * 16 + (lane >> 2);
#pragma unroll
        for (int j = 0; j < 8; ++j) {
            const int d0 = j * 8 + (lane & 3) * 2;
            atomicAdd(&kvp[f0 * HD + d0],       acc[mt][j][0]);
            atomicAdd(&kvp[f0 * HD + d0 + 1],   acc[mt][j][1]);
            atomicAdd(&kvp[(f0 + 8) * HD + d0],     acc[mt][j][2]);
            atomicAdd(&kvp[(f0 + 8) * HD + d0 + 1], acc[mt][j][3]);
        }
        if ((lane & 3) == 0) {
            atomicAdd(&ksum[(size_t)bh * FF + f0],     acc[mt][8][0]);
            atomicAdd(&ksum[(size_t)bh * FF + f0 + 8], acc[mt][8][2]);
        }
    }
}

// ---------------------------------------------------------------------------
// split_kvx: kv fp32 (64 cols) + ksum split (cols 64/65) + zeros -> fp16 [.][72]
// ---------------------------------------------------------------------------
__global__ void __launch_bounds__(256)
split_kvx(const float* __restrict__ kv, const float* __restrict__ ksum,
          __half* __restrict__ kvxh) {
    const int idx = blockIdx.x * 256 + threadIdx.x;    // (bh*256 + f)
    if (idx >= BB * HH * FF) return;
    const float* src = kv + (size_t)idx * HD;
    __half* dh = kvxh + (size_t)idx * 72;
#pragma unroll 8
    for (int c = 0; c < 64; ++c) dh[c] = __float2half_rn(src[c]);
    __half h, l;
    split2(ksum[idx], h, l);
    dh[64] = h; dh[65] = l;
#pragma unroll
    for (int c = 66; c < 72; ++c) dh[c] = __float2half_rn(0.0f);
}

// ---------------------------------------------------------------------------
// out_mma: y = (qp @ kvx) / (col64+col65 + 1e-8). fp16 in/out.
// grid (32 stile, 16 h, 4 b), 256 thr. CTA: 128s x 72d, K=F=256.
// ---------------------------------------------------------------------------
#define OM_KVS 144
#define OM_KVH 0
#define OM_Q (256 * OM_KVS + 64)          // 36928 (+64 slack for dg4 overread)
#define OM_QS 80
#define OM_QSTG 10240                     // q hi only
#define OM_DSMEM (OM_Q + 2 * OM_QSTG)     // 57408

__global__ void __launch_bounds__(256)
out_mma(const __half* __restrict__ Qph, const __half* __restrict__ KVh,
        __half* __restrict__ Yh) {
    extern __shared__ char dsm[];
    const uint32_t sb = smem_u32(dsm);
    const int tid = threadIdx.x;
    const int wid = tid >> 5, lane = tid & 31;
    const int stile = blockIdx.x, h = blockIdx.y, b = blockIdx.z;
    const int bh = b * HH + h;
    const int s0 = stile * 128;

    auto issue_q = [&](int c) {
        const uint32_t st = sb + OM_Q + (c & 1) * OM_QSTG;
#pragma unroll
        for (int q = 0; q < 2; ++q) {
            const int idx = tid * 2 + q;
            const int r = idx >> 2, cc = idx & 3;
            const __half* ph = Qph + ((size_t)bh * SS + s0 + r) * FF + c * 32 + cc * 8;
            cp_async16(st + (uint32_t)r * OM_QS + cc * 16, ph);
        }
        asm volatile("cp.async.commit_group;" ::: "memory");
    };

    {
        const __half* ph = KVh + ((size_t)bh * FF + tid) * 72;
        const uint32_t so = sb + (uint32_t)tid * OM_KVS;
#pragma unroll
        for (int q = 0; q < 9; ++q) cp_async16(so + q * 16, ph + q * 8);
        asm volatile("cp.async.commit_group;" ::: "memory");
    }
    issue_q(0);
    issue_q(1);

    float acc[9][4];
#pragma unroll
    for (int j = 0; j < 9; ++j)
#pragma unroll
        for (int q = 0; q < 4; ++q) acc[j][q] = 0.0f;

    const int lrow = lane & 15, lch = (lane >> 4) * 16;

    for (int c = 0; c < 8; ++c) {
        if (c < 7) { asm volatile("cp.async.wait_group 1;" ::: "memory"); }
        else       { asm volatile("cp.async.wait_group 0;" ::: "memory"); }
        __syncthreads();
        const uint32_t qst = sb + OM_Q + (c & 1) * OM_QSTG;

#pragma unroll
        for (int ks = 0; ks < 2; ++ks) {
            uint32_t ah[4];
            uint32_t ad = qst + (uint32_t)(wid * 16 + lrow) * OM_QS + lch + ks * 32;
            ldm_x4(ah[0], ah[1], ah[2], ah[3], ad);
#pragma unroll
            for (int dg = 0; dg < 5; ++dg) {
                uint32_t bh4[4];
                uint32_t bd = taddr(sb + OM_KVH, OM_KVS, c * 32 + ks * 16, dg * 16, lane);
                ldm_x4_t(bh4[0], bh4[1], bh4[2], bh4[3], bd);
                const int nsel = (dg == 4) ? 1 : 2;
#pragma unroll
                for (int sel = 0; sel < 2; ++sel) {
                    if (sel >= nsel) continue;
                    const int j = dg * 2 + sel;
                    mma16816(acc[j], ah[0], ah[1], ah[2], ah[3], bh4[sel], bh4[sel + 2]);
                }
            }
        }
        __syncthreads();
        if (c + 2 < 8) issue_q(c + 2);
    }

    const int r0 = wid * 16 + (lane >> 2);
    const float den0 = __shfl_sync(0xffffffffu, acc[8][0] + acc[8][1], lane & ~3);
    const float den1 = __shfl_sync(0xffffffffu, acc[8][2] + acc[8][3], lane & ~3);
    const float inv0 = 1.0f / (den0 + 1e-8f);
    const float inv1 = 1.0f / (den1 + 1e-8f);
#pragma unroll
    for (int j = 0; j < 8; ++j) {
        const int col = h * HD + j * 8 + (lane & 3) * 2;
        float o00 = acc[j][0] * inv0, o01 = acc[j][1] * inv0;
        float o10 = acc[j][2] * inv1, o11 = acc[j][3] * inv1;
        size_t off0 = ((size_t)(b * SS + s0 + r0)) * DD + col;
        size_t off1 = ((size_t)(b * SS + s0 + r0 + 8)) * DD + col;
        *(__half2*)(Yh + off0) = __halves2half2(__float2half_rn(o00), __float2half_rn(o01));
        *(__half2*)(Yh + off1) = __halves2half2(__float2half_rn(o10), __float2half_rn(o11));
    }
}

// ---------------------------------------------------------------------------
// fp32 -> fp16 ; zero
// ---------------------------------------------------------------------------
__global__ void __launch_bounds__(256)
split_hi(const float* __restrict__ in, __half* __restrict__ hi, int n) {
    int i = (blockIdx.x * 256 + threadIdx.x) * 4;
    if (i >= n) return;
    float4 v = *(const float4*)(in + i);
    *(__half2*)(hi + i)     = __halves2half2(__float2half_rn(v.x), __float2half_rn(v.y));
    *(__half2*)(hi + i + 2) = __halves2half2(__float2half_rn(v.z), __float2half_rn(v.w));
}
__global__ void zero_kernel(float* __restrict__ p, int n) {
    int i = blockIdx.x * blockDim.x + threadIdx.x;
    if (i < n) p[i] = 0.0f;
}

// ---------------------------------------------------------------------------
// launch
// ---------------------------------------------------------------------------
extern "C" void kernel_launch(void* const* d_in, const int* in_sizes, int n_in,
                              void* d_out, int out_size) {
    const float* x  = (const float*)d_in[0];
    const float* Wq = (const float*)d_in[1];
    const float* bq = (const float*)d_in[2];
    const float* Wk = (const float*)d_in[3];
    const float* bk = (const float*)d_in[4];
    const float* Wv = (const float*)d_in[5];
    const float* bv = (const float*)d_in[6];
    const float* Wo = (const float*)d_in[7];
    const float* bo = (const float*)d_in[8];
    const float* rf = (const float*)d_in[9];
    float* out = (float*)d_out;

    __half *pxh, *pwh, *prfh, *pqh, *pkh, *pvh, *pyh, *pqph, *pkph, *pkvh;
    float *pkv, *pks;
    cudaGetSymbolAddress((void**)&pxh, g_xh);
    cudaGetSymbolAddress((void**)&pwh, g_wh);
    cudaGetSymbolAddress((void**)&prfh, g_rfh);
    cudaGetSymbolAddress((void**)&pqh, g_qh);
    cudaGetSymbolAddress((void**)&pkh, g_kh);
    cudaGetSymbolAddress((void**)&pvh, g_vh);
    cudaGetSymbolAddress((void**)&pyh, g_yh);
    cudaGetSymbolAddress((void**)&pqph, g_qph);
    cudaGetSymbolAddress((void**)&pkph, g_kph);
    cudaGetSymbolAddress((void**)&pkvh, g_kvh);
    cudaGetSymbolAddress((void**)&pkv, g_kv);
    cudaGetSymbolAddress((void**)&pks, g_ksum);

    cudaFuncSetAttribute(gemm_mma_f32, cudaFuncAttributeMaxDynamicSharedMemorySize, GEMM_DSMEM);
    cudaFuncSetAttribute(gemm_mma_h, cudaFuncAttributeMaxDynamicSharedMemorySize, GEMM_DSMEM);
    cudaFuncSetAttribute(phi_mma, cudaFuncAttributeMaxDynamicSharedMemorySize, PH_DSMEM);
    cudaFuncSetAttribute(kv_mma, cudaFuncAttributeMaxDynamicSharedMemorySize, KV_DSMEM);
    cudaFuncSetAttribute(out_mma, cudaFuncAttributeMaxDynamicSharedMemorySize, OM_DSMEM);

    const int WSZ = DD * DD;

    split_hi<<<NN * DD / 4 / 256, 256>>>(x, pxh, NN * DD);
    split_hi<<<4 * WSZ / 4 / 256, 256>>>(Wq, pwh, WSZ);                 // Wq
    split_hi<<<WSZ / 4 / 256, 256>>>(Wk, pwh + 1 * WSZ, WSZ);
    split_hi<<<WSZ / 4 / 256, 256>>>(Wv, pwh + 2 * WSZ, WSZ);
    split_hi<<<WSZ / 4 / 256, 256>>>(Wo, pwh + 3 * WSZ, WSZ);
    split_hi<<<HH * HD * FF / 4 / 256, 256>>>(rf, prfh, HH * HD * FF);

    dim3 gg(DD / 128, NN / 128);
    gemm_mma_h<<<gg, 256, GEMM_DSMEM>>>(pxh, pwh + 0 * WSZ, bq, pqh, DD);
    gemm_mma_h<<<gg, 256, GEMM_DSMEM>>>(pxh, pwh + 1 * WSZ, bk, pkh, DD);
    gemm_mma_h<<<gg, 256, GEMM_DSMEM>>>(pxh, pwh + 2 * WSZ, bv, pvh, DD);

    dim3 pg(SS / 128, 2, BB * HH);
    phi_mma<<<pg, 256, PH_DSMEM>>>(pqh, prfh, pqph);
    phi_mma<<<pg, 256, PH_DSMEM>>>(pkh, prfh, pkph);

    zero_kernel<<<(BB * HH * FF * HD + 255) / 256, 256>>>(pkv, BB * HH * FF * HD);
    zero_kernel<<<(BB * HH * FF + 255) / 256, 256>>>(pks, BB * HH * FF);

    kv_mma<<<dim3(8, HH, BB), 256, KV_DSMEM>>>(pkph, pvh, pkv, pks);

    split_kvx<<<(BB * HH * FF + 255) / 256, 256>>>(pkv, pks, pkvh);

    out_mma<<<dim3(SS / 128, HH, BB), 256, OM_DSMEM>>>(pqph, pkvh, pyh);

    gemm_mma_f32<<<gg, 256, GEMM_DSMEM>>>(pyh, pwh + 3 * WSZ, bo, out, DD);
}

// round 13
// speedup vs baseline: 2.4468x; 1.0195x over previous
#include <cuda_runtime.h>
#include <cuda_fp16.h>
#include <math.h>
#include <stdint.h>

// ---------------------------------------------------------------------------
// Problem constants
// ---------------------------------------------------------------------------
#define BB 4
#define SS 4096
#define DD 1024
#define HH 16
#define FF 256
#define HD 64
#define NN (BB * SS)          // 16384 rows
#define GK 1024               // GEMM K

// ---------------------------------------------------------------------------
// Scratch (device globals; no allocations allowed). Pure fp16 operands;
// only kv/ksum accumulate in fp32 (atomics), ksum re-split into kvx cols 64/65.
// ---------------------------------------------------------------------------
__device__ __half g_xh[NN * DD];
__device__ __half g_wh[4 * DD * DD];
__device__ __half g_rfh[HH * HD * FF];

__device__ __half g_qh[NN * DD];
__device__ __half g_kh[NN * DD];
__device__ __half g_vh[NN * DD];
__device__ __half g_yh[NN * DD];

__device__ __half g_qph[(size_t)BB * HH * SS * FF];
__device__ __half g_kph[(size_t)BB * HH * SS * FF];

__device__ float g_kv[(size_t)BB * HH * FF * HD];     // fp32 (atomics)
__device__ float g_ksum[(size_t)BB * HH * FF];
// extended kv: 72 cols = kv(64) | ksum_hi(64) ksum_lo(65) | zeros(66-71)
__device__ __half g_kvh[(size_t)BB * HH * FF * 72];

// ---------------------------------------------------------------------------
// PTX helpers (base-target: cp.async / ldmatrix / mma.sync)
// ---------------------------------------------------------------------------
__device__ __forceinline__ uint32_t smem_u32(const void* p) {
    return (uint32_t)__cvta_generic_to_shared(p);
}
__device__ __forceinline__ void cp_async16(uint32_t dst, const void* src) {
    asm volatile("cp.async.cg.shared.global [%0], [%1], 16;"
                 :: "r"(dst), "l"(src) : "memory");
}
__device__ __forceinline__ void ldm_x4(uint32_t& r0, uint32_t& r1,
                                       uint32_t& r2, uint32_t& r3, uint32_t addr) {
    asm volatile("ldmatrix.sync.aligned.m8n8.x4.shared.b16 {%0,%1,%2,%3}, [%4];"
                 : "=r"(r0), "=r"(r1), "=r"(r2), "=r"(r3) : "r"(addr));
}
__device__ __forceinline__ void ldm_x4_t(uint32_t& r0, uint32_t& r1,
                                         uint32_t& r2, uint32_t& r3, uint32_t addr) {
    asm volatile("ldmatrix.sync.aligned.m8n8.x4.trans.shared.b16 {%0,%1,%2,%3}, [%4];"
                 : "=r"(r0), "=r"(r1), "=r"(r2), "=r"(r3) : "r"(addr));
}
__device__ __forceinline__ void mma16816(float* c, uint32_t a0, uint32_t a1,
                                         uint32_t a2, uint32_t a3,
                                         uint32_t b0, uint32_t b1) {
    asm volatile(
        "mma.sync.aligned.m16n8k16.row.col.f32.f16.f16.f32 "
        "{%0,%1,%2,%3}, {%4,%5,%6,%7}, {%8,%9}, {%0,%1,%2,%3};"
        : "+f"(c[0]), "+f"(c[1]), "+f"(c[2]), "+f"(c[3])
        : "r"(a0), "r"(a1), "r"(a2), "r"(a3), "r"(b0), "r"(b1));
}
__device__ __forceinline__ uint32_t taddr(uint32_t base, int stride,
                                          int k0, int col0, int lane) {
    int g = lane >> 3, r = lane & 7;
    return base + (uint32_t)((k0 + ((g >> 1) << 3) + r) * stride
                             + (col0 + ((g & 1) << 3)) * 2);
}
__device__ __forceinline__ void split2(float v, __half& h, __half& l) {
    h = __float2half_rn(v);
    l = __float2half_rn(v - __half2float(h));
}
__device__ __forceinline__ float softplusf(float x) {
    return fmaxf(x, 0.0f) + log1pf(expf(-fabsf(x)));
}

// ---------------------------------------------------------------------------
// HMMA single-pass fp16 GEMM-NT: C = A @ B^T + bias.
// 128x128x64 CTA tile, 2 smem tiles per stage (A, B), 3 stages
// -> 110.6 KB smem -> 2 CTAs/SM.
// ---------------------------------------------------------------------------
#define KC 64
#define ROWB 144                         // 128B data + 16B pad; 9 mod 8 = 1
#define TILE_B (128 * ROWB)              // 18432
#define STAGE_B (2 * TILE_B)             // 36864 (A, B)
#define NSTAGE 3
#define GEMM_DSMEM (NSTAGE * STAGE_B)    // 110592 B

template <int HALF_OUT>
__device__ __forceinline__ void gemm_core(
    const __half* __restrict__ A, const __half* __restrict__ B,
    const float* __restrict__ bias, float* __restrict__ C,
    __half* __restrict__ Ch, int Mcols) {
    extern __shared__ char dsm[];
    const uint32_t sbase = smem_u32(dsm);

    const int tid = threadIdx.x;
    const int wid = tid >> 5, lane = tid & 31;
    const int warp_m = wid >> 2;
    const int warp_n = wid & 3;
    const int bm = blockIdx.x * 128;
    const int bn = blockIdx.y * 128;

    const int lrow = lane & 15;
    const int lchunk = (lane >> 4) * 16;

    float acc[4][4][4];
#pragma unroll
    for (int i = 0; i < 4; ++i)
#pragma unroll
        for (int j = 0; j < 4; ++j)
#pragma unroll
            for (int q = 0; q < 4; ++q) acc[i][j][q] = 0.0f;

    const int Lrow = tid >> 1;
    const int Lc = (tid & 1) * 4;
    const int arow = bn + Lrow;
    const int brow = bm + Lrow;

    auto issue_chunk = [&](int c, int stage) {
        const int k0 = c * KC;
        const uint32_t st = sbase + stage * STAGE_B;
        const uint32_t soff = (uint32_t)Lrow * ROWB + Lc * 16;
        const __half* pa = A + (size_t)arow * GK + k0 + Lc * 8;
        const __half* pb = B + (size_t)brow * GK + k0 + Lc * 8;
#pragma unroll
        for (int q = 0; q < 4; ++q) {
            cp_async16(st + soff + q * 16, pa + q * 8);
            cp_async16(st + TILE_B + soff + q * 16, pb + q * 8);
        }
        asm volatile("cp.async.commit_group;" ::: "memory");
    };

    issue_chunk(0, 0);
    issue_chunk(1, 1);

    const int NCH = GK / KC;     // 16
    for (int c = 0; c < NCH; ++c) {
        if (c + 1 < NCH) { asm volatile("cp.async.wait_group 1;" ::: "memory"); }
        else             { asm volatile("cp.async.wait_group 0;" ::: "memory"); }
        __syncthreads();

        const uint32_t st = sbase + (c % NSTAGE) * STAGE_B;
        const uint32_t a_base = st + (uint32_t)(warp_m * 64 + lrow) * ROWB + lchunk;
        const uint32_t b_base = st + TILE_B + (uint32_t)(warp_n * 32 + lrow) * ROWB + lchunk;

#pragma unroll
        for (int s = 0; s < 4; ++s) {
            uint32_t ah[4][4];
#pragma unroll
            for (int i = 0; i < 4; ++i) {
                uint32_t ad = a_base + (uint32_t)i * 16 * ROWB + s * 32;
                ldm_x4(ah[i][0], ah[i][1], ah[i][2], ah[i][3], ad);
            }
            uint32_t bh[2][4];
#pragma unroll
            for (int j2 = 0; j2 < 2; ++j2) {
                uint32_t bd = b_base + (uint32_t)j2 * 16 * ROWB + s * 32;
                ldm_x4(bh[j2][0], bh[j2][1], bh[j2][2], bh[j2][3], bd);
            }
#pragma unroll
            for (int i = 0; i < 4; ++i) {
#pragma unroll
                for (int j = 0; j < 4; ++j) {
                    const int j2 = j >> 1, sel = j & 1;
                    mma16816(acc[i][j], ah[i][0], ah[i][1], ah[i][2], ah[i][3],
                             bh[j2][sel], bh[j2][sel + 2]);
                }
            }
        }
        __syncthreads();
        if (c + 2 < NCH) issue_chunk(c + 2, (c + 2) % NSTAGE);
    }

#pragma unroll
    for (int i = 0; i < 4; ++i) {
#pragma unroll
        for (int j = 0; j < 4; ++j) {
            const int row0 = bn + warp_m * 64 + i * 16 + (lane >> 2);
            const int col = bm + warp_n * 32 + j * 8 + (lane & 3) * 2;
            const float2 bv = *(const float2*)(bias + col);
            float o00 = acc[i][j][0] + bv.x, o01 = acc[i][j][1] + bv.y;
            float o10 = acc[i][j][2] + bv.x, o11 = acc[i][j][3] + bv.y;
            if (HALF_OUT) {
                *(__half2*)(Ch + (size_t)row0 * Mcols + col) =
                    __halves2half2(__float2half_rn(o00), __float2half_rn(o01));
                *(__half2*)(Ch + (size_t)(row0 + 8) * Mcols + col) =
                    __halves2half2(__float2half_rn(o10), __float2half_rn(o11));
            } else {
                *(float2*)(C + (size_t)row0 * Mcols + col) = make_float2(o00, o01);
                *(float2*)(C + (size_t)(row0 + 8) * Mcols + col) = make_float2(o10, o11);
            }
        }
    }
}

// fused Q/K/V projection: grid (8, 128, 3); z selects weight/bias/output
__global__ void __launch_bounds__(256, 2)
gemm_qkv(const __half* __restrict__ A, const __half* __restrict__ W,
         const float* __restrict__ bq, const float* __restrict__ bk,
         const float* __restrict__ bv,
         __half* __restrict__ Q, __half* __restrict__ K, __half* __restrict__ V) {
    const int which = blockIdx.z;
    const __half* B = W + (size_t)which * DD * DD;
    const float* bias = (which == 0) ? bq : (which == 1) ? bk : bv;
    __half* Ch = (which == 0) ? Q : (which == 1) ? K : V;
    gemm_core<1>(A, B, bias, nullptr, Ch, DD);
}
__global__ void __launch_bounds__(256, 2)
gemm_mma_f32(const __half* A, const __half* B,
             const float* bias, float* C, int Mcols) {
    gemm_core<0>(A, B, bias, C, nullptr, Mcols);
}

// ---------------------------------------------------------------------------
// phi_mma: qp = softplus(q @ rf), fp16 in/out. FUSED q'/k' launch:
// grid (32 stile, 2 fchunk, 128): z = path*64 + bh. CTA: 128s x 128f, K=64.
// ---------------------------------------------------------------------------
#define PH_QS 144
#define PH_RS 272
#define PH_RFH (128 * PH_QS)                // 18432
#define PH_DSMEM (PH_RFH + 64 * PH_RS)      // 35840

__global__ void __launch_bounds__(256)
phi_mma(const __half* __restrict__ Qh, const __half* __restrict__ Kh,
        const __half* __restrict__ RFh,
        __half* __restrict__ Pq, __half* __restrict__ Pk) {
    extern __shared__ char dsm[];
    const uint32_t sb = smem_u32(dsm);
    const int tid = threadIdx.x;
    const int wid = tid >> 5, lane = tid & 31;
    const int stile = blockIdx.x, fc = blockIdx.y;
    const int zz = blockIdx.z;
    const int bh = zz & 63;
    const __half* In = (zz < 64) ? Qh : Kh;
    __half* Ph = (zz < 64) ? Pq : Pk;
    const int b = bh >> 4, h = bh & 15;
    const int s0 = stile * 128;

    {
        const int r = tid >> 1, c0 = (tid & 1) * 4;
        const __half* ph = In + ((size_t)(b * SS + s0 + r)) * DD + h * HD + c0 * 8;
        const uint32_t so = sb + (uint32_t)r * PH_QS + c0 * 16;
#pragma unroll
        for (int q = 0; q < 4; ++q) cp_async16(so + q * 16, ph + q * 8);
    }
    {
        const int r = tid >> 2, c0 = (tid & 3) * 4;
        const __half* ph = RFh + (size_t)h * HD * FF + (size_t)r * FF + fc * 128 + c0 * 8;
        const uint32_t so = sb + PH_RFH + (uint32_t)r * PH_RS + c0 * 16;
#pragma unroll
        for (int q = 0; q < 4; ++q) cp_async16(so + q * 16, ph + q * 8);
    }
    asm volatile("cp.async.commit_group;" ::: "memory");
    asm volatile("cp.async.wait_group 0;" ::: "memory");
    __syncthreads();

    float acc[16][4];
#pragma unroll
    for (int j = 0; j < 16; ++j)
#pragma unroll
        for (int q = 0; q < 4; ++q) acc[j][q] = 0.0f;

    const int lrow = lane & 15, lch = (lane >> 4) * 16;
    const uint32_t a_base = sb + (uint32_t)(wid * 16 + lrow) * PH_QS + lch;

#pragma unroll
    for (int ks = 0; ks < 4; ++ks) {
        uint32_t ah[4];
        ldm_x4(ah[0], ah[1], ah[2], ah[3], a_base + ks * 32);
#pragma unroll
        for (int ft = 0; ft < 8; ++ft) {
            uint32_t bh4[4];
            uint32_t bd = taddr(sb + PH_RFH, PH_RS, ks * 16, ft * 16, lane);
            ldm_x4_t(bh4[0], bh4[1], bh4[2], bh4[3], bd);
#pragma unroll
            for (int sel = 0; sel < 2; ++sel) {
                const int j = ft * 2 + sel;
                mma16816(acc[j], ah[0], ah[1], ah[2], ah[3], bh4[sel], bh4[sel + 2]);
            }
        }
    }

    const int r0 = wid * 16 + (lane >> 2);
#pragma unroll
    for (int j = 0; j < 16; ++j) {
        const int col = fc * 128 + j * 8 + (lane & 3) * 2;
        float s00 = softplusf(acc[j][0]), s01 = softplusf(acc[j][1]);
        float s10 = softplusf(acc[j][2]), s11 = softplusf(acc[j][3]);
        size_t o0 = ((size_t)bh * SS + s0 + r0) * FF + col;
        size_t o1 = ((size_t)bh * SS + s0 + r0 + 8) * FF + col;
        *(__half2*)(Ph + o0) = __halves2half2(__float2half_rn(s00), __float2half_rn(s01));
        *(__half2*)(Ph + o1) = __halves2half2(__float2half_rn(s10), __float2half_rn(s11));
    }
}

// ---------------------------------------------------------------------------
// kv_mma: kv[f,d] += sum_s kp[s,f]*v[s,d]; ksum via ones column (col 64 of V).
// fp16 in, fp32 atomics out. grid (8, 16, 4), 256 thr.
// ---------------------------------------------------------------------------
#define KV_KS 528
#define KV_VS 144
#define KV_KH 0
#define KV_VH 16896
#define KV_STG (KV_VH + 32 * KV_VS + 32)  // 21536
#define KV_DSMEM (2 * KV_STG)             // 43072

__global__ void __launch_bounds__(256)
kv_mma(const __half* __restrict__ Kph, const __half* __restrict__ Vh,
       float* __restrict__ kv, float* __restrict__ ksum) {
    extern __shared__ char dsm[];
    const uint32_t sb = smem_u32(dsm);
    const int tid = threadIdx.x;
    const int wid = tid >> 5, lane = tid & 31;
    const int chunk = blockIdx.x, h = blockIdx.y, b = blockIdx.z;
    const int bh = b * HH + h;
    const int sbase0 = chunk * 512;

    if (tid < 64) {
        const int stg = tid >> 5, r = tid & 31;
        const uint32_t bvh = sb + stg * KV_STG + KV_VH + r * KV_VS + 128;
        asm volatile("st.shared.v4.b32 [%0], {%1,%2,%3,%4};"
                     :: "r"(bvh), "r"(0x00003C00u), "r"(0u), "r"(0u), "r"(0u));
    }

    auto issue = [&](int t, int stg) {
        const int s0 = sbase0 + t * 32;
        const uint32_t st = sb + stg * KV_STG;
        const int r = tid >> 3;
        {
            const int c0 = (tid & 7) * 4;
            const __half* ph = Kph + ((size_t)bh * SS + s0 + r) * FF + c0 * 8;
            const uint32_t so = st + (uint32_t)r * KV_KS + c0 * 16;
#pragma unroll
            for (int q = 0; q < 4; ++q) cp_async16(so + q * 16, ph + q * 8);
        }
        {
            const int c = tid & 7;
            const __half* ph = Vh + ((size_t)(b * SS + s0 + r)) * DD + h * HD + c * 8;
            cp_async16(st + KV_VH + (uint32_t)r * KV_VS + c * 16, ph);
        }
        asm volatile("cp.async.commit_group;" ::: "memory");
    };

    float acc[2][9][4];
#pragma unroll
    for (int i = 0; i < 2; ++i)
#pragma unroll
        for (int j = 0; j < 9; ++j)
#pragma unroll
            for (int q = 0; q < 4; ++q) acc[i][j][q] = 0.0f;

    issue(0, 0);
    for (int t = 0; t < 16; ++t) {
        if (t + 1 < 16) issue(t + 1, (t + 1) & 1);
        if (t + 1 < 16) { asm volatile("cp.async.wait_group 1;" ::: "memory"); }
        else            { asm volatile("cp.async.wait_group 0;" ::: "memory"); }
        __syncthreads();
        const uint32_t st = sb + (t & 1) * KV_STG;

#pragma unroll
        for (int ks = 0; ks < 2; ++ks) {
            uint32_t ah[2][4];
#pragma unroll
            for (int mt = 0; mt < 2; ++mt) {
                uint32_t ad = taddr(st + KV_KH, KV_KS, ks * 16, wid * 32 + mt * 16, lane);
                ldm_x4_t(ah[mt][0], ah[mt][1], ah[mt][2], ah[mt][3], ad);
            }
#pragma unroll
            for (int dg = 0; dg < 5; ++dg) {
                uint32_t bh4[4];
                uint32_t bd = taddr(st + KV_VH, KV_VS, ks * 16, dg * 16, lane);
                ldm_x4_t(bh4[0], bh4[1], bh4[2], bh4[3], bd);
                const int nsel = (dg == 4) ? 1 : 2;
#pragma unroll
                for (int mt = 0; mt < 2; ++mt) {
#pragma unroll
                    for (int sel = 0; sel < 2; ++sel) {
                        if (sel >= nsel) continue;
                        const int j = dg * 2 + sel;
                        mma16816(acc[mt][j], ah[mt][0], ah[mt][1], ah[mt][2], ah[mt][3],
                                 bh4[sel], bh4[sel + 2]);
                    }
                }
            }
        }
        __syncthreads();
    }

    float* kvp = kv + (size_t)bh * FF * HD;
#pragma unroll
    for (int mt = 0; mt < 2; ++mt) {
        const int f0 = wid * 32 + mt * 16 + (lane >> 2);
#pragma unroll
        for (int j = 0; j < 8; ++j) {
            const int d0 = j * 8 + (lane & 3) * 2;
            atomicAdd(&kvp[f0 * HD + d0],       acc[mt][j][0]);
            atomicAdd(&kvp[f0 * HD + d0 + 1],   acc[mt][j][1]);
            atomicAdd(&kvp[(f0 + 8) * HD + d0],     acc[mt][j][2]);
            atomicAdd(&kvp[(f0 + 8) * HD + d0 + 1], acc[mt][j][3]);
        }
        if ((lane & 3) == 0) {
            atomicAdd(&ksum[(size_t)bh * FF + f0],     acc[mt][8][0]);
            atomicAdd(&ksum[(size_t)bh * FF + f0 + 8], acc[mt][8][2]);
        }
    }
}

// ---------------------------------------------------------------------------
// split_kvx: kv fp32 (64 cols) + ksum split (cols 64/65) + zeros -> fp16 [.][72]
// ---------------------------------------------------------------------------
__global__ void __launch_bounds__(256)
split_kvx(const float* __restrict__ kv, const float* __restrict__ ksum,
          __half* __restrict__ kvxh) {
    const int idx = blockIdx.x * 256 + threadIdx.x;    // (bh*256 + f)
    if (idx >= BB * HH * FF) return;
    const float* src = kv + (size_t)idx * HD;
    __half* dh = kvxh + (size_t)idx * 72;
#pragma unroll 8
    for (int c = 0; c < 64; ++c) dh[c] = __float2half_rn(src[c]);
    __half h, l;
    split2(ksum[idx], h, l);
    dh[64] = h; dh[65] = l;
#pragma unroll
    for (int c = 66; c < 72; ++c) dh[c] = __float2half_rn(0.0f);
}

// ---------------------------------------------------------------------------
// out_mma: y = (qp @ kvx) / (col64+col65 + 1e-8). fp16 in/out.
// grid (32 stile, 16 h, 4 b), 256 thr. CTA: 128s x 72d, K=F=256.
// ---------------------------------------------------------------------------
#define OM_KVS 144
#define OM_KVH 0
#define OM_Q (256 * OM_KVS + 64)          // 36928 (+64 slack for dg4 overread)
#define OM_QS 80
#define OM_QSTG 10240                     // q hi only
#define OM_DSMEM (OM_Q + 2 * OM_QSTG)     // 57408

__global__ void __launch_bounds__(256)
out_mma(const __half* __restrict__ Qph, const __half* __restrict__ KVh,
        __half* __restrict__ Yh) {
    extern __shared__ char dsm[];
    const uint32_t sb = smem_u32(dsm);
    const int tid = threadIdx.x;
    const int wid = tid >> 5, lane = tid & 31;
    const int stile = blockIdx.x, h = blockIdx.y, b = blockIdx.z;
    const int bh = b * HH + h;
    const int s0 = stile * 128;

    auto issue_q = [&](int c) {
        const uint32_t st = sb + OM_Q + (c & 1) * OM_QSTG;
#pragma unroll
        for (int q = 0; q < 2; ++q) {
            const int idx = tid * 2 + q;
            const int r = idx >> 2, cc = idx & 3;
            const __half* ph = Qph + ((size_t)bh * SS + s0 + r) * FF + c * 32 + cc * 8;
            cp_async16(st + (uint32_t)r * OM_QS + cc * 16, ph);
        }
        asm volatile("cp.async.commit_group;" ::: "memory");
    };

    {
        const __half* ph = KVh + ((size_t)bh * FF + tid) * 72;
        const uint32_t so = sb + (uint32_t)tid * OM_KVS;
#pragma unroll
        for (int q = 0; q < 9; ++q) cp_async16(so + q * 16, ph + q * 8);
        asm volatile("cp.async.commit_group;" ::: "memory");
    }
    issue_q(0);
    issue_q(1);

    float acc[9][4];
#pragma unroll
    for (int j = 0; j < 9; ++j)
#pragma unroll
        for (int q = 0; q < 4; ++q) acc[j][q] = 0.0f;

    const int lrow = lane & 15, lch = (lane >> 4) * 16;

    for (int c = 0; c < 8; ++c) {
        if (c < 7) { asm volatile("cp.async.wait_group 1;" ::: "memory"); }
        else       { asm volatile("cp.async.wait_group 0;" ::: "memory"); }
        __syncthreads();
        const uint32_t qst = sb + OM_Q + (c & 1) * OM_QSTG;

#pragma unroll
        for (int ks = 0; ks < 2; ++ks) {
            uint32_t ah[4];
            uint32_t ad = qst + (uint32_t)(wid * 16 + lrow) * OM_QS + lch + ks * 32;
            ldm_x4(ah[0], ah[1], ah[2], ah[3], ad);
#pragma unroll
            for (int dg = 0; dg < 5; ++dg) {
                uint32_t bh4[4];
                uint32_t bd = taddr(sb + OM_KVH, OM_KVS, c * 32 + ks * 16, dg * 16, lane);
                ldm_x4_t(bh4[0], bh4[1], bh4[2], bh4[3], bd);
                const int nsel = (dg == 4) ? 1 : 2;
#pragma unroll
                for (int sel = 0; sel < 2; ++sel) {
                    if (sel >= nsel) continue;
                    const int j = dg * 2 + sel;
                    mma16816(acc[j], ah[0], ah[1], ah[2], ah[3], bh4[sel], bh4[sel + 2]);
                }
            }
        }
        __syncthreads();
        if (c + 2 < 8) issue_q(c + 2);
    }

    const int r0 = wid * 16 + (lane >> 2);
    const float den0 = __shfl_sync(0xffffffffu, acc[8][0] + acc[8][1], lane & ~3);
    const float den1 = __shfl_sync(0xffffffffu, acc[8][2] + acc[8][3], lane & ~3);
    const float inv0 = 1.0f / (den0 + 1e-8f);
    const float inv1 = 1.0f / (den1 + 1e-8f);
#pragma unroll
    for (int j = 0; j < 8; ++j) {
        const int col = h * HD + j * 8 + (lane & 3) * 2;
        float o00 = acc[j][0] * inv0, o01 = acc[j][1] * inv0;
        float o10 = acc[j][2] * inv1, o11 = acc[j][3] * inv1;
        size_t off0 = ((size_t)(b * SS + s0 + r0)) * DD + col;
        size_t off1 = ((size_t)(b * SS + s0 + r0 + 8)) * DD + col;
        *(__half2*)(Yh + off0) = __halves2half2(__float2half_rn(o00), __float2half_rn(o01));
        *(__half2*)(Yh + off1) = __halves2half2(__float2half_rn(o10), __float2half_rn(o11));
    }
}

// ---------------------------------------------------------------------------
// fp32 -> fp16 ; zero (kv + ksum fused)
// ---------------------------------------------------------------------------
__global__ void __launch_bounds__(256)
split_hi(const float* __restrict__ in, __half* __restrict__ hi, int n) {
    int i = (blockIdx.x * 256 + threadIdx.x) * 4;
    if (i >= n) return;
    float4 v = *(const float4*)(in + i);
    *(__half2*)(hi + i)     = __halves2half2(__float2half_rn(v.x), __float2half_rn(v.y));
    *(__half2*)(hi + i + 2) = __halves2half2(__float2half_rn(v.z), __float2half_rn(v.w));
}
__global__ void zero2_kernel(float* __restrict__ p1, int n1,
                             float* __restrict__ p2, int n2) {
    int i = blockIdx.x * blockDim.x + threadIdx.x;
    if (i < n1) p1[i] = 0.0f;
    if (i < n2) p2[i] = 0.0f;
}

// ---------------------------------------------------------------------------
// launch
// ---------------------------------------------------------------------------
extern "C" void kernel_launch(void* const* d_in, const int* in_sizes, int n_in,
                              void* d_out, int out_size) {
    const float* x  = (const float*)d_in[0];
    const float* Wq = (const float*)d_in[1];
    const float* bq = (const float*)d_in[2];
    const float* Wk = (const float*)d_in[3];
    const float* bk = (const float*)d_in[4];
    const float* Wv = (const float*)d_in[5];
    const float* bv = (const float*)d_in[6];
    const float* Wo = (const float*)d_in[7];
    const float* bo = (const float*)d_in[8];
    const float* rf = (const float*)d_in[9];
    float* out = (float*)d_out;

    __half *pxh, *pwh, *prfh, *pqh, *pkh, *pvh, *pyh, *pqph, *pkph, *pkvh;
    float *pkv, *pks;
    cudaGetSymbolAddress((void**)&pxh, g_xh);
    cudaGetSymbolAddress((void**)&pwh, g_wh);
    cudaGetSymbolAddress((void**)&prfh, g_rfh);
    cudaGetSymbolAddress((void**)&pqh, g_qh);
    cudaGetSymbolAddress((void**)&pkh, g_kh);
    cudaGetSymbolAddress((void**)&pvh, g_vh);
    cudaGetSymbolAddress((void**)&pyh, g_yh);
    cudaGetSymbolAddress((void**)&pqph, g_qph);
    cudaGetSymbolAddress((void**)&pkph, g_kph);
    cudaGetSymbolAddress((void**)&pkvh, g_kvh);
    cudaGetSymbolAddress((void**)&pkv, g_kv);
    cudaGetSymbolAddress((void**)&pks, g_ksum);

    cudaFuncSetAttribute(gemm_qkv, cudaFuncAttributeMaxDynamicSharedMemorySize, GEMM_DSMEM);
    cudaFuncSetAttribute(gemm_mma_f32, cudaFuncAttributeMaxDynamicSharedMemorySize, GEMM_DSMEM);
    cudaFuncSetAttribute(phi_mma, cudaFuncAttributeMaxDynamicSharedMemorySize, PH_DSMEM);
    cudaFuncSetAttribute(kv_mma, cudaFuncAttributeMaxDynamicSharedMemorySize, KV_DSMEM);
    cudaFuncSetAttribute(out_mma, cudaFuncAttributeMaxDynamicSharedMemorySize, OM_DSMEM);

    const int WSZ = DD * DD;

    split_hi<<<NN * DD / 4 / 256, 256>>>(x, pxh, NN * DD);
    split_hi<<<WSZ / 4 / 256, 256>>>(Wq, pwh + 0 * WSZ, WSZ);
    split_hi<<<WSZ / 4 / 256, 256>>>(Wk, pwh + 1 * WSZ, WSZ);
    split_hi<<<WSZ / 4 / 256, 256>>>(Wv, pwh + 2 * WSZ, WSZ);
    split_hi<<<WSZ / 4 / 256, 256>>>(Wo, pwh + 3 * WSZ, WSZ);
    split_hi<<<HH * HD * FF / 4 / 256, 256>>>(rf, prfh, HH * HD * FF);

    zero2_kernel<<<(BB * HH * FF * HD + 255) / 256, 256>>>(
        pkv, BB * HH * FF * HD, pks, BB * HH * FF);

    // fused Q/K/V projections
    gemm_qkv<<<dim3(DD / 128, NN / 128, 3), 256, GEMM_DSMEM>>>(
        pxh, pwh, bq, bk, bv, pqh, pkh, pvh);

    // fused q'/k' feature maps
    phi_mma<<<dim3(SS / 128, 2, 128), 256, PH_DSMEM>>>(
        pqh, pkh, prfh, pqph, pkph);

    kv_mma<<<dim3(8, HH, BB), 256, KV_DSMEM>>>(pkph, pvh, pkv, pks);

    split_kvx<<<(BB * HH * FF + 255) / 256, 256>>>(pkv, pks, pkvh);

    out_mma<<<dim3(SS / 128, HH, BB), 256, OM_DSMEM>>>(pqph, pkvh, pyh);

    gemm_mma_f32<<<dim3(DD / 128, NN / 128), 256, GEMM_DSMEM>>>(
        pyh, pwh + 3 * WSZ, bo, out, DD);
}

// round 14
// speedup vs baseline: 2.4852x; 1.0157x over previous
#include <cuda_runtime.h>
#include <cuda_fp16.h>
#include <math.h>
#include <stdint.h>

// ---------------------------------------------------------------------------
// Problem constants
// ---------------------------------------------------------------------------
#define BB 4
#define SS 4096
#define DD 1024
#define HH 16
#define FF 256
#define HD 64
#define NN (BB * SS)          // 16384 rows
#define GK 1024               // GEMM K

// ---------------------------------------------------------------------------
// Scratch (device globals; no allocations allowed). Pure fp16 operands;
// only kv/ksum accumulate in fp32 (atomics), ksum re-split into kvx cols 64/65.
// ---------------------------------------------------------------------------
__device__ __half g_xh[NN * DD];
__device__ __half g_wh[4 * DD * DD];
__device__ __half g_rfh[HH * HD * FF];

__device__ __half g_qh[NN * DD];
__device__ __half g_kh[NN * DD];
__device__ __half g_vh[NN * DD];
__device__ __half g_yh[NN * DD];

__device__ __half g_qph[(size_t)BB * HH * SS * FF];
__device__ __half g_kph[(size_t)BB * HH * SS * FF];

__device__ float g_kv[(size_t)BB * HH * FF * HD];     // fp32 (atomics)
__device__ float g_ksum[(size_t)BB * HH * FF];
// extended kv: 72 cols = kv(64) | ksum_hi(64) ksum_lo(65) | zeros(66-71)
__device__ __half g_kvh[(size_t)BB * HH * FF * 72];

// ---------------------------------------------------------------------------
// PTX helpers (base-target: cp.async / ldmatrix / mma.sync)
// ---------------------------------------------------------------------------
__device__ __forceinline__ uint32_t smem_u32(const void* p) {
    return (uint32_t)__cvta_generic_to_shared(p);
}
__device__ __forceinline__ void cp_async16(uint32_t dst, const void* src) {
    asm volatile("cp.async.cg.shared.global [%0], [%1], 16;"
                 :: "r"(dst), "l"(src) : "memory");
}
__device__ __forceinline__ void ldm_x4(uint32_t& r0, uint32_t& r1,
                                       uint32_t& r2, uint32_t& r3, uint32_t addr) {
    asm volatile("ldmatrix.sync.aligned.m8n8.x4.shared.b16 {%0,%1,%2,%3}, [%4];"
                 : "=r"(r0), "=r"(r1), "=r"(r2), "=r"(r3) : "r"(addr));
}
__device__ __forceinline__ void ldm_x4_t(uint32_t& r0, uint32_t& r1,
                                         uint32_t& r2, uint32_t& r3, uint32_t addr) {
    asm volatile("ldmatrix.sync.aligned.m8n8.x4.trans.shared.b16 {%0,%1,%2,%3}, [%4];"
                 : "=r"(r0), "=r"(r1), "=r"(r2), "=r"(r3) : "r"(addr));
}
__device__ __forceinline__ void mma16816(float* c, uint32_t a0, uint32_t a1,
                                         uint32_t a2, uint32_t a3,
                                         uint32_t b0, uint32_t b1) {
    asm volatile(
        "mma.sync.aligned.m16n8k16.row.col.f32.f16.f16.f32 "
        "{%0,%1,%2,%3}, {%4,%5,%6,%7}, {%8,%9}, {%0,%1,%2,%3};"
        : "+f"(c[0]), "+f"(c[1]), "+f"(c[2]), "+f"(c[3])
        : "r"(a0), "r"(a1), "r"(a2), "r"(a3), "r"(b0), "r"(b1));
}
__device__ __forceinline__ uint32_t taddr(uint32_t base, int stride,
                                          int k0, int col0, int lane) {
    int g = lane >> 3, r = lane & 7;
    return base + (uint32_t)((k0 + ((g >> 1) << 3) + r) * stride
                             + (col0 + ((g & 1) << 3)) * 2);
}
__device__ __forceinline__ void split2(float v, __half& h, __half& l) {
    h = __float2half_rn(v);
    l = __float2half_rn(v - __half2float(h));
}
__device__ __forceinline__ float softplusf(float x) {
    return fmaxf(x, 0.0f) + log1pf(expf(-fabsf(x)));
}

// ---------------------------------------------------------------------------
// HMMA single-pass fp16 GEMM-NT: C = A @ B^T + bias.
// 128x128x64 CTA tile, 2 smem tiles per stage (A, B), 3 stages
// -> 110.6 KB smem -> 2 CTAs/SM. Single barrier per chunk; cp.async for
// chunk c+2 issued BEFORE compute of chunk c (stage (c+2)%3 was consumed
// in chunk c-1, ordered by this iteration's barrier).
// ---------------------------------------------------------------------------
#define KC 64
#define ROWB 144                         // 128B data + 16B pad; 9 mod 8 = 1
#define TILE_B (128 * ROWB)              // 18432
#define STAGE_B (2 * TILE_B)             // 36864 (A, B)
#define NSTAGE 3
#define GEMM_DSMEM (NSTAGE * STAGE_B)    // 110592 B

template <int HALF_OUT>
__device__ __forceinline__ void gemm_core(
    const __half* __restrict__ A, const __half* __restrict__ B,
    const float* __restrict__ bias, float* __restrict__ C,
    __half* __restrict__ Ch, int Mcols) {
    extern __shared__ char dsm[];
    const uint32_t sbase = smem_u32(dsm);

    const int tid = threadIdx.x;
    const int wid = tid >> 5, lane = tid & 31;
    const int warp_m = wid >> 2;
    const int warp_n = wid & 3;
    const int bm = blockIdx.x * 128;
    const int bn = blockIdx.y * 128;

    const int lrow = lane & 15;
    const int lchunk = (lane >> 4) * 16;

    float acc[4][4][4];
#pragma unroll
    for (int i = 0; i < 4; ++i)
#pragma unroll
        for (int j = 0; j < 4; ++j)
#pragma unroll
            for (int q = 0; q < 4; ++q) acc[i][j][q] = 0.0f;

    const int Lrow = tid >> 1;
    const int Lc = (tid & 1) * 4;
    const int arow = bn + Lrow;
    const int brow = bm + Lrow;

    auto issue_chunk = [&](int c, int stage) {
        const int k0 = c * KC;
        const uint32_t st = sbase + stage * STAGE_B;
        const uint32_t soff = (uint32_t)Lrow * ROWB + Lc * 16;
        const __half* pa = A + (size_t)arow * GK + k0 + Lc * 8;
        const __half* pb = B + (size_t)brow * GK + k0 + Lc * 8;
#pragma unroll
        for (int q = 0; q < 4; ++q) {
            cp_async16(st + soff + q * 16, pa + q * 8);
            cp_async16(st + TILE_B + soff + q * 16, pb + q * 8);
        }
        asm volatile("cp.async.commit_group;" ::: "memory");
    };

    issue_chunk(0, 0);
    issue_chunk(1, 1);

    const int NCH = GK / KC;     // 16
    for (int c = 0; c < NCH; ++c) {
        if (c + 1 < NCH) { asm volatile("cp.async.wait_group 1;" ::: "memory"); }
        else             { asm volatile("cp.async.wait_group 0;" ::: "memory"); }
        __syncthreads();
        if (c + 2 < NCH) issue_chunk(c + 2, (c + 2) % NSTAGE);

        const uint32_t st = sbase + (c % NSTAGE) * STAGE_B;
        const uint32_t a_base = st + (uint32_t)(warp_m * 64 + lrow) * ROWB + lchunk;
        const uint32_t b_base = st + TILE_B + (uint32_t)(warp_n * 32 + lrow) * ROWB + lchunk;

#pragma unroll
        for (int s = 0; s < 4; ++s) {
            uint32_t ah[4][4];
#pragma unroll
            for (int i = 0; i < 4; ++i) {
                uint32_t ad = a_base + (uint32_t)i * 16 * ROWB + s * 32;
                ldm_x4(ah[i][0], ah[i][1], ah[i][2], ah[i][3], ad);
            }
            uint32_t bh[2][4];
#pragma unroll
            for (int j2 = 0; j2 < 2; ++j2) {
                uint32_t bd = b_base + (uint32_t)j2 * 16 * ROWB + s * 32;
                ldm_x4(bh[j2][0], bh[j2][1], bh[j2][2], bh[j2][3], bd);
            }
#pragma unroll
            for (int i = 0; i < 4; ++i) {
#pragma unroll
                for (int j = 0; j < 4; ++j) {
                    const int j2 = j >> 1, sel = j & 1;
                    mma16816(acc[i][j], ah[i][0], ah[i][1], ah[i][2], ah[i][3],
                             bh[j2][sel], bh[j2][sel + 2]);
                }
            }
        }
    }

#pragma unroll
    for (int i = 0; i < 4; ++i) {
#pragma unroll
        for (int j = 0; j < 4; ++j) {
            const int row0 = bn + warp_m * 64 + i * 16 + (lane >> 2);
            const int col = bm + warp_n * 32 + j * 8 + (lane & 3) * 2;
            const float2 bv = *(const float2*)(bias + col);
            float o00 = acc[i][j][0] + bv.x, o01 = acc[i][j][1] + bv.y;
            float o10 = acc[i][j][2] + bv.x, o11 = acc[i][j][3] + bv.y;
            if (HALF_OUT) {
                *(__half2*)(Ch + (size_t)row0 * Mcols + col) =
                    __halves2half2(__float2half_rn(o00), __float2half_rn(o01));
                *(__half2*)(Ch + (size_t)(row0 + 8) * Mcols + col) =
                    __halves2half2(__float2half_rn(o10), __float2half_rn(o11));
            } else {
                *(float2*)(C + (size_t)row0 * Mcols + col) = make_float2(o00, o01);
                *(float2*)(C + (size_t)(row0 + 8) * Mcols + col) = make_float2(o10, o11);
            }
        }
    }
}

// fused Q/K/V projection: grid (8, 128, 3); z selects weight/bias/output
__global__ void __launch_bounds__(256, 2)
gemm_qkv(const __half* __restrict__ A, const __half* __restrict__ W,
         const float* __restrict__ bq, const float* __restrict__ bk,
         const float* __restrict__ bv,
         __half* __restrict__ Q, __half* __restrict__ K, __half* __restrict__ V) {
    const int which = blockIdx.z;
    const __half* B = W + (size_t)which * DD * DD;
    const float* bias = (which == 0) ? bq : (which == 1) ? bk : bv;
    __half* Ch = (which == 0) ? Q : (which == 1) ? K : V;
    gemm_core<1>(A, B, bias, nullptr, Ch, DD);
}
__global__ void __launch_bounds__(256, 2)
gemm_mma_f32(const __half* A, const __half* B,
             const float* bias, float* C, int Mcols) {
    gemm_core<0>(A, B, bias, C, nullptr, Mcols);
}

// ---------------------------------------------------------------------------
// phi_mma: qp = softplus(q @ rf), fp16 in/out. FUSED q'/k' launch:
// grid (32 stile, 2 fchunk, 128): z = path*64 + bh. CTA: 128s x 128f, K=64.
// ---------------------------------------------------------------------------
#define PH_QS 144
#define PH_RS 272
#define PH_RFH (128 * PH_QS)                // 18432
#define PH_DSMEM (PH_RFH + 64 * PH_RS)      // 35840

__global__ void __launch_bounds__(256)
phi_mma(const __half* __restrict__ Qh, const __half* __restrict__ Kh,
        const __half* __restrict__ RFh,
        __half* __restrict__ Pq, __half* __restrict__ Pk) {
    extern __shared__ char dsm[];
    const uint32_t sb = smem_u32(dsm);
    const int tid = threadIdx.x;
    const int wid = tid >> 5, lane = tid & 31;
    const int stile = blockIdx.x, fc = blockIdx.y;
    const int zz = blockIdx.z;
    const int bh = zz & 63;
    const __half* In = (zz < 64) ? Qh : Kh;
    __half* Ph = (zz < 64) ? Pq : Pk;
    const int b = bh >> 4, h = bh & 15;
    const int s0 = stile * 128;

    {
        const int r = tid >> 1, c0 = (tid & 1) * 4;
        const __half* ph = In + ((size_t)(b * SS + s0 + r)) * DD + h * HD + c0 * 8;
        const uint32_t so = sb + (uint32_t)r * PH_QS + c0 * 16;
#pragma unroll
        for (int q = 0; q < 4; ++q) cp_async16(so + q * 16, ph + q * 8);
    }
    {
        const int r = tid >> 2, c0 = (tid & 3) * 4;
        const __half* ph = RFh + (size_t)h * HD * FF + (size_t)r * FF + fc * 128 + c0 * 8;
        const uint32_t so = sb + PH_RFH + (uint32_t)r * PH_RS + c0 * 16;
#pragma unroll
        for (int q = 0; q < 4; ++q) cp_async16(so + q * 16, ph + q * 8);
    }
    asm volatile("cp.async.commit_group;" ::: "memory");
    asm volatile("cp.async.wait_group 0;" ::: "memory");
    __syncthreads();

    float acc[16][4];
#pragma unroll
    for (int j = 0; j < 16; ++j)
#pragma unroll
        for (int q = 0; q < 4; ++q) acc[j][q] = 0.0f;

    const int lrow = lane & 15, lch = (lane >> 4) * 16;
    const uint32_t a_base = sb + (uint32_t)(wid * 16 + lrow) * PH_QS + lch;

#pragma unroll
    for (int ks = 0; ks < 4; ++ks) {
        uint32_t ah[4];
        ldm_x4(ah[0], ah[1], ah[2], ah[3], a_base + ks * 32);
#pragma unroll
        for (int ft = 0; ft < 8; ++ft) {
            uint32_t bh4[4];
            uint32_t bd = taddr(sb + PH_RFH, PH_RS, ks * 16, ft * 16, lane);
            ldm_x4_t(bh4[0], bh4[1], bh4[2], bh4[3], bd);
#pragma unroll
            for (int sel = 0; sel < 2; ++sel) {
                const int j = ft * 2 + sel;
                mma16816(acc[j], ah[0], ah[1], ah[2], ah[3], bh4[sel], bh4[sel + 2]);
            }
        }
    }

    const int r0 = wid * 16 + (lane >> 2);
#pragma unroll
    for (int j = 0; j < 16; ++j) {
        const int col = fc * 128 + j * 8 + (lane & 3) * 2;
        float s00 = softplusf(acc[j][0]), s01 = softplusf(acc[j][1]);
        float s10 = softplusf(acc[j][2]), s11 = softplusf(acc[j][3]);
        size_t o0 = ((size_t)bh * SS + s0 + r0) * FF + col;
        size_t o1 = ((size_t)bh * SS + s0 + r0 + 8) * FF + col;
        *(__half2*)(Ph + o0) = __halves2half2(__float2half_rn(s00), __float2half_rn(s01));
        *(__half2*)(Ph + o1) = __halves2half2(__float2half_rn(s10), __float2half_rn(s11));
    }
}

// ---------------------------------------------------------------------------
// kv_mma: kv[f,d] += sum_s kp[s,f]*v[s,d]; ksum via ones column (col 64 of V).
// fp16 in, fp32 atomics out. grid (8, 16, 4), 256 thr.
// ---------------------------------------------------------------------------
#define KV_KS 528
#define KV_VS 144
#define KV_KH 0
#define KV_VH 16896
#define KV_STG (KV_VH + 32 * KV_VS + 32)  // 21536
#define KV_DSMEM (2 * KV_STG)             // 43072

__global__ void __launch_bounds__(256)
kv_mma(const __half* __restrict__ Kph, const __half* __restrict__ Vh,
       float* __restrict__ kv, float* __restrict__ ksum) {
    extern __shared__ char dsm[];
    const uint32_t sb = smem_u32(dsm);
    const int tid = threadIdx.x;
    const int wid = tid >> 5, lane = tid & 31;
    const int chunk = blockIdx.x, h = blockIdx.y, b = blockIdx.z;
    const int bh = b * HH + h;
    const int sbase0 = chunk * 512;

    if (tid < 64) {
        const int stg = tid >> 5, r = tid & 31;
        const uint32_t bvh = sb + stg * KV_STG + KV_VH + r * KV_VS + 128;
        asm volatile("st.shared.v4.b32 [%0], {%1,%2,%3,%4};"
                     :: "r"(bvh), "r"(0x00003C00u), "r"(0u), "r"(0u), "r"(0u));
    }

    auto issue = [&](int t, int stg) {
        const int s0 = sbase0 + t * 32;
        const uint32_t st = sb + stg * KV_STG;
        const int r = tid >> 3;
        {
            const int c0 = (tid & 7) * 4;
            const __half* ph = Kph + ((size_t)bh * SS + s0 + r) * FF + c0 * 8;
            const uint32_t so = st + (uint32_t)r * KV_KS + c0 * 16;
#pragma unroll
            for (int q = 0; q < 4; ++q) cp_async16(so + q * 16, ph + q * 8);
        }
        {
            const int c = tid & 7;
            const __half* ph = Vh + ((size_t)(b * SS + s0 + r)) * DD + h * HD + c * 8;
            cp_async16(st + KV_VH + (uint32_t)r * KV_VS + c * 16, ph);
        }
        asm volatile("cp.async.commit_group;" ::: "memory");
    };

    float acc[2][9][4];
#pragma unroll
    for (int i = 0; i < 2; ++i)
#pragma unroll
        for (int j = 0; j < 9; ++j)
#pragma unroll
            for (int q = 0; q < 4; ++q) acc[i][j][q] = 0.0f;

    issue(0, 0);
    for (int t = 0; t < 16; ++t) {
        if (t + 1 < 16) issue(t + 1, (t + 1) & 1);
        if (t + 1 < 16) { asm volatile("cp.async.wait_group 1;" ::: "memory"); }
        else            { asm volatile("cp.async.wait_group 0;" ::: "memory"); }
        __syncthreads();
        const uint32_t st = sb + (t & 1) * KV_STG;

#pragma unroll
        for (int ks = 0; ks < 2; ++ks) {
            uint32_t ah[2][4];
#pragma unroll
            for (int mt = 0; mt < 2; ++mt) {
                uint32_t ad = taddr(st + KV_KH, KV_KS, ks * 16, wid * 32 + mt * 16, lane);
                ldm_x4_t(ah[mt][0], ah[mt][1], ah[mt][2], ah[mt][3], ad);
            }
#pragma unroll
            for (int dg = 0; dg < 5; ++dg) {
                uint32_t bh4[4];
                uint32_t bd = taddr(st + KV_VH, KV_VS, ks * 16, dg * 16, lane);
                ldm_x4_t(bh4[0], bh4[1], bh4[2], bh4[3], bd);
                const int nsel = (dg == 4) ? 1 : 2;
#pragma unroll
                for (int mt = 0; mt < 2; ++mt) {
#pragma unroll
                    for (int sel = 0; sel < 2; ++sel) {
                        if (sel >= nsel) continue;
                        const int j = dg * 2 + sel;
                        mma16816(acc[mt][j], ah[mt][0], ah[mt][1], ah[mt][2], ah[mt][3],
                                 bh4[sel], bh4[sel + 2]);
                    }
                }
            }
        }
        __syncthreads();
    }

    float* kvp = kv + (size_t)bh * FF * HD;
#pragma unroll
    for (int mt = 0; mt < 2; ++mt) {
        const int f0 = wid * 32 + mt * 16 + (lane >> 2);
#pragma unroll
        for (int j = 0; j < 8; ++j) {
            const int d0 = j * 8 + (lane & 3) * 2;
            atomicAdd(&kvp[f0 * HD + d0],       acc[mt][j][0]);
            atomicAdd(&kvp[f0 * HD + d0 + 1],   acc[mt][j][1]);
            atomicAdd(&kvp[(f0 + 8) * HD + d0],     acc[mt][j][2]);
            atomicAdd(&kvp[(f0 + 8) * HD + d0 + 1], acc[mt][j][3]);
        }
        if ((lane & 3) == 0) {
            atomicAdd(&ksum[(size_t)bh * FF + f0],     acc[mt][8][0]);
            atomicAdd(&ksum[(size_t)bh * FF + f0 + 8], acc[mt][8][2]);
        }
    }
}

// ---------------------------------------------------------------------------
// split_kvx: kv fp32 (64 cols) + ksum split (cols 64/65) + zeros -> fp16 [.][72]
// ---------------------------------------------------------------------------
__global__ void __launch_bounds__(256)
split_kvx(const float* __restrict__ kv, const float* __restrict__ ksum,
          __half* __restrict__ kvxh) {
    const int idx = blockIdx.x * 256 + threadIdx.x;    // (bh*256 + f)
    if (idx >= BB * HH * FF) return;
    const float* src = kv + (size_t)idx * HD;
    __half* dh = kvxh + (size_t)idx * 72;
#pragma unroll 8
    for (int c = 0; c < 64; ++c) dh[c] = __float2half_rn(src[c]);
    __half h, l;
    split2(ksum[idx], h, l);
    dh[64] = h; dh[65] = l;
#pragma unroll
    for (int c = 66; c < 72; ++c) dh[c] = __float2half_rn(0.0f);
}

// ---------------------------------------------------------------------------
// out_mma: y = (qp @ kvx) / (col64+col65 + 1e-8). fp16 in/out.
// grid (32 stile, 16 h, 4 b), 256 thr. CTA: 128s x 72d, K=F=256.
// q pipeline: 3 stages, single barrier, issue-before-compute.
// ---------------------------------------------------------------------------
#define OM_KVS 144
#define OM_KVH 0
#define OM_Q (256 * OM_KVS + 64)          // 36928 (+64 slack for dg4 overread)
#define OM_QS 80
#define OM_QSTG 10240                     // q hi only
#define OM_NSTG 3
#define OM_DSMEM (OM_Q + OM_NSTG * OM_QSTG)   // 67648

__global__ void __launch_bounds__(256)
out_mma(const __half* __restrict__ Qph, const __half* __restrict__ KVh,
        __half* __restrict__ Yh) {
    extern __shared__ char dsm[];
    const uint32_t sb = smem_u32(dsm);
    const int tid = threadIdx.x;
    const int wid = tid >> 5, lane = tid & 31;
    const int stile = blockIdx.x, h = blockIdx.y, b = blockIdx.z;
    const int bh = b * HH + h;
    const int s0 = stile * 128;

    auto issue_q = [&](int c) {
        const uint32_t st = sb + OM_Q + (c % OM_NSTG) * OM_QSTG;
#pragma unroll
        for (int q = 0; q < 2; ++q) {
            const int idx = tid * 2 + q;
            const int r = idx >> 2, cc = idx & 3;
            const __half* ph = Qph + ((size_t)bh * SS + s0 + r) * FF + c * 32 + cc * 8;
            cp_async16(st + (uint32_t)r * OM_QS + cc * 16, ph);
        }
        asm volatile("cp.async.commit_group;" ::: "memory");
    };

    {
        const __half* ph = KVh + ((size_t)bh * FF + tid) * 72;
        const uint32_t so = sb + (uint32_t)tid * OM_KVS;
#pragma unroll
        for (int q = 0; q < 9; ++q) cp_async16(so + q * 16, ph + q * 8);
        asm volatile("cp.async.commit_group;" ::: "memory");
    }
    issue_q(0);
    issue_q(1);

    float acc[9][4];
#pragma unroll
    for (int j = 0; j < 9; ++j)
#pragma unroll
        for (int q = 0; q < 4; ++q) acc[j][q] = 0.0f;

    const int lrow = lane & 15, lch = (lane >> 4) * 16;

    for (int c = 0; c < 8; ++c) {
        if (c < 7) { asm volatile("cp.async.wait_group 1;" ::: "memory"); }
        else       { asm volatile("cp.async.wait_group 0;" ::: "memory"); }
        __syncthreads();
        if (c + 2 < 8) issue_q(c + 2);
        const uint32_t qst = sb + OM_Q + (c % OM_NSTG) * OM_QSTG;

#pragma unroll
        for (int ks = 0; ks < 2; ++ks) {
            uint32_t ah[4];
            uint32_t ad = qst + (uint32_t)(wid * 16 + lrow) * OM_QS + lch + ks * 32;
            ldm_x4(ah[0], ah[1], ah[2], ah[3], ad);
#pragma unroll
            for (int dg = 0; dg < 5; ++dg) {
                uint32_t bh4[4];
                uint32_t bd = taddr(sb + OM_KVH, OM_KVS, c * 32 + ks * 16, dg * 16, lane);
                ldm_x4_t(bh4[0], bh4[1], bh4[2], bh4[3], bd);
                const int nsel = (dg == 4) ? 1 : 2;
#pragma unroll
                for (int sel = 0; sel < 2; ++sel) {
                    if (sel >= nsel) continue;
                    const int j = dg * 2 + sel;
                    mma16816(acc[j], ah[0], ah[1], ah[2], ah[3], bh4[sel], bh4[sel + 2]);
                }
            }
        }
    }

    const int r0 = wid * 16 + (lane >> 2);
    const float den0 = __shfl_sync(0xffffffffu, acc[8][0] + acc[8][1], lane & ~3);
    const float den1 = __shfl_sync(0xffffffffu, acc[8][2] + acc[8][3], lane & ~3);
    const float inv0 = 1.0f / (den0 + 1e-8f);
    const float inv1 = 1.0f / (den1 + 1e-8f);
#pragma unroll
    for (int j = 0; j < 8; ++j) {
        const int col = h * HD + j * 8 + (lane & 3) * 2;
        float o00 = acc[j][0] * inv0, o01 = acc[j][1] * inv0;
        float o10 = acc[j][2] * inv1, o11 = acc[j][3] * inv1;
        size_t off0 = ((size_t)(b * SS + s0 + r0)) * DD + col;
        size_t off1 = ((size_t)(b * SS + s0 + r0 + 8)) * DD + col;
        *(__half2*)(Yh + off0) = __halves2half2(__float2half_rn(o00), __float2half_rn(o01));
        *(__half2*)(Yh + off1) = __halves2half2(__float2half_rn(o10), __float2half_rn(o11));
    }
}

// ---------------------------------------------------------------------------
// fp32 -> fp16 ; fused 4-weight split ; zero (kv + ksum fused)
// ---------------------------------------------------------------------------
__global__ void __launch_bounds__(256)
split_hi(const float* __restrict__ in, __half* __restrict__ hi, int n) {
    int i = (blockIdx.x * 256 + threadIdx.x) * 4;
    if (i >= n) return;
    float4 v = *(const float4*)(in + i);
    *(__half2*)(hi + i)     = __halves2half2(__float2half_rn(v.x), __float2half_rn(v.y));
    *(__half2*)(hi + i + 2) = __halves2half2(__float2half_rn(v.z), __float2half_rn(v.w));
}
__global__ void __launch_bounds__(256)
split_w4(const float* __restrict__ w0, const float* __restrict__ w1,
         const float* __restrict__ w2, const float* __restrict__ w3,
         __half* __restrict__ out) {
    const int which = blockIdx.y;
    const float* src = (which == 0) ? w0 : (which == 1) ? w1 : (which == 2) ? w2 : w3;
    __half* dst = out + (size_t)which * DD * DD;
    int i = (blockIdx.x * 256 + threadIdx.x) * 4;
    float4 v = *(const float4*)(src + i);
    *(__half2*)(dst + i)     = __halves2half2(__float2half_rn(v.x), __float2half_rn(v.y));
    *(__half2*)(dst + i + 2) = __halves2half2(__float2half_rn(v.z), __float2half_rn(v.w));
}
__global__ void zero2_kernel(float* __restrict__ p1, int n1,
                             float* __restrict__ p2, int n2) {
    int i = blockIdx.x * blockDim.x + threadIdx.x;
    if (i < n1) p1[i] = 0.0f;
    if (i < n2) p2[i] = 0.0f;
}

// ---------------------------------------------------------------------------
// launch
// ---------------------------------------------------------------------------
extern "C" void kernel_launch(void* const* d_in, const int* in_sizes, int n_in,
                              void* d_out, int out_size) {
    const float* x  = (const float*)d_in[0];
    const float* Wq = (const float*)d_in[1];
    const float* bq = (const float*)d_in[2];
    const float* Wk = (const float*)d_in[3];
    const float* bk = (const float*)d_in[4];
    const float* Wv = (const float*)d_in[5];
    const float* bv = (const float*)d_in[6];
    const float* Wo = (const float*)d_in[7];
    const float* bo = (const float*)d_in[8];
    const float* rf = (const float*)d_in[9];
    float* out = (float*)d_out;

    __half *pxh, *pwh, *prfh, *pqh, *pkh, *pvh, *pyh, *pqph, *pkph, *pkvh;
    float *pkv, *pks;
    cudaGetSymbolAddress((void**)&pxh, g_xh);
    cudaGetSymbolAddress((void**)&pwh, g_wh);
    cudaGetSymbolAddress((void**)&prfh, g_rfh);
    cudaGetSymbolAddress((void**)&pqh, g_qh);
    cudaGetSymbolAddress((void**)&pkh, g_kh);
    cudaGetSymbolAddress((void**)&pvh, g_vh);
    cudaGetSymbolAddress((void**)&pyh, g_yh);
    cudaGetSymbolAddress((void**)&pqph, g_qph);
    cudaGetSymbolAddress((void**)&pkph, g_kph);
    cudaGetSymbolAddress((void**)&pkvh, g_kvh);
    cudaGetSymbolAddress((void**)&pkv, g_kv);
    cudaGetSymbolAddress((void**)&pks, g_ksum);

    cudaFuncSetAttribute(gemm_qkv, cudaFuncAttributeMaxDynamicSharedMemorySize, GEMM_DSMEM);
    cudaFuncSetAttribute(gemm_mma_f32, cudaFuncAttributeMaxDynamicSharedMemorySize, GEMM_DSMEM);
    cudaFuncSetAttribute(phi_mma, cudaFuncAttributeMaxDynamicSharedMemorySize, PH_DSMEM);
    cudaFuncSetAttribute(kv_mma, cudaFuncAttributeMaxDynamicSharedMemorySize, KV_DSMEM);
    cudaFuncSetAttribute(out_mma, cudaFuncAttributeMaxDynamicSharedMemorySize, OM_DSMEM);

    const int WSZ = DD * DD;

    split_hi<<<NN * DD / 4 / 256, 256>>>(x, pxh, NN * DD);
    split_w4<<<dim3(WSZ / 4 / 256, 4), 256>>>(Wq, Wk, Wv, Wo, pwh);
    split_hi<<<HH * HD * FF / 4 / 256, 256>>>(rf, prfh, HH * HD * FF);

    zero2_kernel<<<(BB * HH * FF * HD + 255) / 256, 256>>>(
        pkv, BB * HH * FF * HD, pks, BB * HH * FF);

    // fused Q/K/V projections
    gemm_qkv<<<dim3(DD / 128, NN / 128, 3), 256, GEMM_DSMEM>>>(
        pxh, pwh, bq, bk, bv, pqh, pkh, pvh);

    // fused q'/k' feature maps
    phi_mma<<<dim3(SS / 128, 2, 128), 256, PH_DSMEM>>>(
        pqh, pkh, prfh, pqph, pkph);

    kv_mma<<<dim3(8, HH, BB), 256, KV_DSMEM>>>(pkph, pvh, pkv, pks);

    split_kvx<<<(BB * HH * FF + 255) / 256, 256>>>(pkv, pks, pkvh);

    out_mma<<<dim3(SS / 128, HH, BB), 256, OM_DSMEM>>>(pqph, pkvh, pyh);

    gemm_mma_f32<<<dim3(DD / 128, NN / 128), 256, GEMM_DSMEM>>>(
        pyh, pwh + 3 * WSZ, bo, out, DD);
}